// round 7
// baseline (speedup 1.0000x reference)
#include <cuda_runtime.h>
#include <cuda_fp16.h>
#include <cstdint>

// ---------------- problem constants ----------------
#define N_NODES 100000
#define N_EDGES 1600000
#define C_IN    500
#define C       40        // n_classes
#define H       64        // hidden
#define ALPHA   0.1f
#define K_HOPS  10

// ---------------- static scratch (no allocations allowed) ----------------
__device__ __half g_h0h[N_NODES * C];       // h0 in fp16
__device__ __half g_bufA[N_NODES * C];      // hop ping
__device__ __half g_bufB[N_NODES * C];      // hop pong
__device__ int    g_deg[2 * N_NODES];       // [0..N) deg_out, [N..2N) deg_in
__device__ float  g_inv_out[N_NODES];
__device__ float  g_inv_in[N_NODES];
__device__ int    g_off[N_NODES + 1];
__device__ int    g_cursor[N_NODES];
__device__ int2   g_csr[N_EDGES];           // (src, bits(norm))

// ============================================================
// 1) scores = x @ Wb + bb   [N, 40]
//    2 rows/thread, packed fma.rn.f32x2 accumulators.
// ============================================================
#define GB_T 128
#define WKT  100

__global__ __launch_bounds__(GB_T, 2) void gemm_kernel(
    const float* __restrict__ x, const float* __restrict__ Wb,
    const float* __restrict__ bb, float* __restrict__ scores)
{
    __shared__ __align__(16) float Wt[WKT * C];
    __shared__ float bs[C];

    const int tid = threadIdx.x;
    if (tid < C) bs[tid] = bb[tid];

    const int r0 = blockIdx.x * 256 + tid;          // always < N (grid=391)
    const int r1 = r0 + 128;
    const size_t r1c = (r1 < N_NODES) ? (size_t)r1 : (size_t)(N_NODES - 1);
    const float4* xa_p = (const float4*)(x + (size_t)r0 * C_IN);
    const float4* xb_p = (const float4*)(x + r1c * C_IN);

    unsigned long long acc0[C / 2], acc1[C / 2];
#pragma unroll
    for (int j = 0; j < C / 2; j++) { acc0[j] = 0ull; acc1[j] = 0ull; }

#pragma unroll 1
    for (int t = 0; t < C_IN / WKT; t++) {          // 5 tiles of K=100
        __syncthreads();
        const float4* wsrc = (const float4*)(Wb + t * WKT * C);
        for (int i = tid; i < WKT * C / 4; i += GB_T)
            ((float4*)Wt)[i] = wsrc[i];
        __syncthreads();

#pragma unroll 1
        for (int kg = 0; kg < WKT / 4; kg++) {      // 25 groups of 4 k's
            const float4 xa = __ldg(xa_p + t * (WKT / 4) + kg);
            const float4 xb = __ldg(xb_p + t * (WKT / 4) + kg);
#pragma unroll
            for (int j = 0; j < 4; j++) {
                const float fa = j == 0 ? xa.x : j == 1 ? xa.y : j == 2 ? xa.z : xa.w;
                const float fb = j == 0 ? xb.x : j == 1 ? xb.y : j == 2 ? xb.z : xb.w;
                unsigned long long xa2, xb2;
                asm("mov.b64 %0, {%1, %1};" : "=l"(xa2) : "f"(fa));
                asm("mov.b64 %0, {%1, %1};" : "=l"(xb2) : "f"(fb));
                const ulonglong2* wr = (const ulonglong2*)(Wt + (kg * 4 + j) * C);
#pragma unroll
                for (int p = 0; p < C / 4; p++) {   // 10 LDS.128 = 20 pairs
                    const ulonglong2 w = wr[p];
                    asm("fma.rn.f32x2 %0, %1, %2, %0;" : "+l"(acc0[2*p  ]) : "l"(w.x), "l"(xa2));
                    asm("fma.rn.f32x2 %0, %1, %2, %0;" : "+l"(acc0[2*p+1]) : "l"(w.y), "l"(xa2));
                    asm("fma.rn.f32x2 %0, %1, %2, %0;" : "+l"(acc1[2*p  ]) : "l"(w.x), "l"(xb2));
                    asm("fma.rn.f32x2 %0, %1, %2, %0;" : "+l"(acc1[2*p+1]) : "l"(w.y), "l"(xb2));
                }
            }
        }
    }

    float o0[C], o1[C];
#pragma unroll
    for (int j = 0; j < C / 2; j++) {
        float lo, hi;
        asm("mov.b64 {%0, %1}, %2;" : "=f"(lo), "=f"(hi) : "l"(acc0[j]));
        o0[2*j] = lo + bs[2*j]; o0[2*j+1] = hi + bs[2*j+1];
        asm("mov.b64 {%0, %1}, %2;" : "=f"(lo), "=f"(hi) : "l"(acc1[j]));
        o1[2*j] = lo + bs[2*j]; o1[2*j+1] = hi + bs[2*j+1];
    }
    float4* d0 = (float4*)(scores + (size_t)r0 * C);
#pragma unroll
    for (int c4 = 0; c4 < C / 4; c4++)
        d0[c4] = make_float4(o0[c4*4], o0[c4*4+1], o0[c4*4+2], o0[c4*4+3]);
    if (r1 < N_NODES) {
        float4* d1 = (float4*)(scores + (size_t)r1 * C);
#pragma unroll
        for (int c4 = 0; c4 < C / 4; c4++)
            d1[c4] = make_float4(o1[c4*4], o1[c4*4+1], o1[c4*4+2], o1[c4*4+3]);
    }
}

// ============================================================
// 2) h0 = relu(softmax(scores) @ W1 + b1) @ W2 + b2  -> fp16
// ============================================================
#define MLP_BS 128
__global__ __launch_bounds__(MLP_BS) void mlp_kernel(
    const float* __restrict__ scores,
    const float* __restrict__ W1, const float* __restrict__ b1,
    const float* __restrict__ W2, const float* __restrict__ b2)
{
    __shared__ float W1s[C * H];
    __shared__ float W2s[H * C];
    __shared__ float b1s[H];
    __shared__ float b2s[C];
    __shared__ float p_sh[C * MLP_BS];

    const int tid = threadIdx.x;
    for (int i = tid; i < C * H; i += MLP_BS) W1s[i] = W1[i];
    for (int i = tid; i < H * C; i += MLP_BS) W2s[i] = W2[i];
    if (tid < H) b1s[tid] = b1[tid];
    if (tid < C) b2s[tid] = b2[tid];
    __syncthreads();

    const int node = blockIdx.x * MLP_BS + tid;
    if (node >= N_NODES) return;

    const float4* sc4 = (const float4*)(scores + (size_t)node * C);
    float m = -1e30f;
#pragma unroll
    for (int q = 0; q < C / 4; q++) {
        const float4 v = sc4[q];
        p_sh[(q * 4 + 0) * MLP_BS + tid] = v.x;
        p_sh[(q * 4 + 1) * MLP_BS + tid] = v.y;
        p_sh[(q * 4 + 2) * MLP_BS + tid] = v.z;
        p_sh[(q * 4 + 3) * MLP_BS + tid] = v.w;
        m = fmaxf(m, fmaxf(fmaxf(v.x, v.y), fmaxf(v.z, v.w)));
    }
    float s = 0.f;
    for (int i = 0; i < C; i++) {
        const float e = __expf(p_sh[i * MLP_BS + tid] - m);
        p_sh[i * MLP_BS + tid] = e;
        s += e;
    }
    const float inv = 1.f / s;

    float h1[H];
#pragma unroll
    for (int j = 0; j < H; j++) h1[j] = b1s[j];
    for (int i = 0; i < C; i++) {
        const float pv = p_sh[i * MLP_BS + tid] * inv;
#pragma unroll
        for (int j = 0; j < H; j++) h1[j] += pv * W1s[i * H + j];
    }
#pragma unroll
    for (int j = 0; j < H; j++) h1[j] = fmaxf(h1[j], 0.f);

    float o[C];
    for (int c = 0; c < C; c++) {
        float a = b2s[c];
#pragma unroll
        for (int j = 0; j < H; j++) a += h1[j] * W2s[j * C + c];
        o[c] = a;
    }

    uint4 pk[5];
    uint32_t* pw = (uint32_t*)pk;
#pragma unroll
    for (int p = 0; p < C / 2; p++) {
        const __half2 hv = __floats2half2_rn(o[2 * p], o[2 * p + 1]);
        pw[p] = *(const uint32_t*)&hv;
    }
    uint4* hrow = (uint4*)(g_h0h + (size_t)node * C);
#pragma unroll
    for (int p = 0; p < 5; p++) hrow[p] = pk[p];
}

// ============================================================
// 3) degrees
// ============================================================
__global__ void deg_kernel(const int* __restrict__ src, const int* __restrict__ dst)
{
    const int e = blockIdx.x * blockDim.x + threadIdx.x;
    if (e < N_EDGES) {
        atomicAdd(&g_deg[src[e]], 1);
        atomicAdd(&g_deg[N_NODES + dst[e]], 1);
    }
}

// ============================================================
// 4) fused: inv-sqrt + exclusive scan -> offsets + cursor
// ============================================================
#define SCAN_T 1024
__global__ __launch_bounds__(SCAN_T) void scan_fused_kernel()
{
    __shared__ int part[SCAN_T];
    const int t = threadIdx.x;

    for (int i = t; i < N_NODES; i += SCAN_T) {
        const int d_o = g_deg[i];
        const int d_i = g_deg[N_NODES + i];
        g_inv_out[i] = d_o > 0 ? rsqrtf((float)d_o) : 0.f;
        g_inv_in[i]  = d_i > 0 ? rsqrtf((float)d_i) : 0.f;
    }

    const int CH = (N_NODES + SCAN_T - 1) / SCAN_T;
    const int base = t * CH;
    int s = 0;
    for (int i = 0; i < CH; i++) {
        const int idx = base + i;
        if (idx < N_NODES) s += g_deg[N_NODES + idx];
    }
    part[t] = s;
    __syncthreads();
    for (int o = 1; o < SCAN_T; o <<= 1) {
        const int v = (t >= o) ? part[t - o] : 0;
        __syncthreads();
        part[t] += v;
        __syncthreads();
    }
    int excl = part[t] - s;
    for (int i = 0; i < CH; i++) {
        const int idx = base + i;
        if (idx < N_NODES) {
            g_off[idx] = excl;
            g_cursor[idx] = excl;
            excl += g_deg[N_NODES + idx];
        }
    }
    if (t == SCAN_T - 1) g_off[N_NODES] = part[SCAN_T - 1];
}

// ============================================================
// 5) CSR fill (single 8B scatter per edge)
// ============================================================
__global__ void fill_csr_kernel(const int* __restrict__ src, const int* __restrict__ dst)
{
    const int e = blockIdx.x * blockDim.x + threadIdx.x;
    if (e < N_EDGES) {
        const int s = src[e];
        const int d = dst[e];
        const int pos = atomicAdd(&g_cursor[d], 1);
        g_csr[pos] = make_int2(s, __float_as_int(g_inv_out[s] * g_inv_in[d]));
    }
}

// ============================================================
// 6) one APPNP hop: one WARP per node, 3 edge-groups x 10 lanes,
//    uint2 (4 halfs) per lane. Corrected cross-group reduction:
//    both shuffles read the PRE-update value.
// ============================================================
#define HOP_BS 256

template <bool LAST>
__global__ __launch_bounds__(HOP_BS) void hop_kernel(
    const __half* __restrict__ hin, const __half* __restrict__ h0,
    __half* __restrict__ hout_h, float* __restrict__ hout_f)
{
    const int node = blockIdx.x * (HOP_BS / 32) + (threadIdx.x >> 5);
    const int lane = threadIdx.x & 31;
    const int eg = lane / 10;               // 0..2 active; lanes 30,31 idle
    const int q  = lane % 10;               // uint2 index within 80B row
    // N_NODES = 100000 = 12500 * 8 -> grid exact, no bounds check needed

    const int beg = __ldg(&g_off[node]);
    const int end = __ldg(&g_off[node + 1]);

    float a0 = 0.f, a1 = 0.f, a2 = 0.f, a3 = 0.f;
    if (eg < 3) {
        const uint2* base = (const uint2*)hin;
#pragma unroll 2
        for (int e = beg + eg; e < end; e += 3) {
            const int2 en = __ldg(&g_csr[e]);          // broadcast in group
            const float nrm = __int_as_float(en.y);
            const uint2 hv = __ldg(base + (size_t)en.x * 10 + q);
            const float2 f0 = __half22float2(*(const __half2*)&hv.x);
            const float2 f1 = __half22float2(*(const __half2*)&hv.y);
            a0 += nrm * f0.x; a1 += nrm * f0.y;
            a2 += nrm * f1.x; a3 += nrm * f1.y;
        }
    }

    // correct reduction: shuffle ORIGINAL values, then sum.
    {
        const float b0 = __shfl_down_sync(0xffffffffu, a0, 10);
        const float c0 = __shfl_down_sync(0xffffffffu, a0, 20);
        const float b1 = __shfl_down_sync(0xffffffffu, a1, 10);
        const float c1 = __shfl_down_sync(0xffffffffu, a1, 20);
        const float b2 = __shfl_down_sync(0xffffffffu, a2, 10);
        const float c2 = __shfl_down_sync(0xffffffffu, a2, 20);
        const float b3 = __shfl_down_sync(0xffffffffu, a3, 10);
        const float c3 = __shfl_down_sync(0xffffffffu, a3, 20);
        a0 += b0 + c0; a1 += b1 + c1; a2 += b2 + c2; a3 += b3 + c3;
    }

    if (lane < 10) {
        const uint2 h0v = __ldg((const uint2*)h0 + (size_t)node * 10 + lane);
        const float2 g0 = __half22float2(*(const __half2*)&h0v.x);
        const float2 g1 = __half22float2(*(const __half2*)&h0v.y);
        const float o0 = (1.f - ALPHA) * a0 + ALPHA * g0.x;
        const float o1 = (1.f - ALPHA) * a1 + ALPHA * g0.y;
        const float o2 = (1.f - ALPHA) * a2 + ALPHA * g1.x;
        const float o3 = (1.f - ALPHA) * a3 + ALPHA * g1.y;
        if (LAST) {
            ((float4*)(hout_f + (size_t)node * C))[lane] = make_float4(o0, o1, o2, o3);
        } else {
            uint2 pk;
            const __half2 p0 = __floats2half2_rn(o0, o1);
            const __half2 p1 = __floats2half2_rn(o2, o3);
            pk.x = *(const uint32_t*)&p0;
            pk.y = *(const uint32_t*)&p1;
            ((uint2*)hout_h)[(size_t)node * 10 + lane] = pk;
        }
    }
}

// ============================================================
// launch
// ============================================================
extern "C" void kernel_launch(void* const* d_in, const int* in_sizes, int n_in,
                              void* d_out, int out_size)
{
    const float* x  = (const float*)d_in[0];
    const int*   ei = (const int*)d_in[1];
    const float* Wb = (const float*)d_in[2];
    const float* bb = (const float*)d_in[3];
    const float* W1 = (const float*)d_in[4];
    const float* b1 = (const float*)d_in[5];
    const float* W2 = (const float*)d_in[6];
    const float* b2 = (const float*)d_in[7];

    float* out = (float*)d_out;
    float* adjust = out;                              // [N, 40]
    float* scores = out + (size_t)N_NODES * C;        // [N, 40]

    const int* src = ei;
    const int* dst = ei + N_EDGES;

    __half *h0p, *Ap, *Bp;
    int *degp;
    cudaGetSymbolAddress((void**)&h0p, g_h0h);
    cudaGetSymbolAddress((void**)&Ap, g_bufA);
    cudaGetSymbolAddress((void**)&Bp, g_bufB);
    cudaGetSymbolAddress((void**)&degp, g_deg);

    // order: memset(1), deg(2), scan(3), fill(4), gemm(5), mlp(6), hop0(7)...
    cudaMemsetAsync(degp, 0, 2 * N_NODES * sizeof(int), 0);

    deg_kernel<<<(N_EDGES + 255) / 256, 256>>>(src, dst);
    scan_fused_kernel<<<1, SCAN_T>>>();
    fill_csr_kernel<<<(N_EDGES + 255) / 256, 256>>>(src, dst);

    gemm_kernel<<<(N_NODES + 255) / 256, GB_T>>>(x, Wb, bb, scores);
    mlp_kernel<<<(N_NODES + MLP_BS - 1) / MLP_BS, MLP_BS>>>(scores, W1, b1, W2, b2);

    const int hop_grid = N_NODES / (HOP_BS / 32);     // 12500, exact
    const __half* hin = h0p;
    for (int k = 0; k < K_HOPS; k++) {
        if (k == K_HOPS - 1) {
            hop_kernel<true><<<hop_grid, HOP_BS>>>(hin, h0p, nullptr, adjust);
        } else {
            __half* o = (k % 2 == 0) ? Ap : Bp;
            hop_kernel<false><<<hop_grid, HOP_BS>>>(hin, h0p, o, nullptr);
            hin = o;
        }
    }
}

// round 8
// speedup vs baseline: 1.1414x; 1.1414x over previous
#include <cuda_runtime.h>
#include <cuda_fp16.h>
#include <cstdint>

// ---------------- problem constants ----------------
#define N_NODES 100000
#define N_EDGES 1600000
#define C_IN    500
#define C       40        // n_classes
#define H       64        // hidden
#define ALPHA   0.1f
#define K_HOPS  10

// ---------------- static scratch (no allocations allowed) ----------------
__device__ __half  g_h0h[N_NODES * C];      // h0 (plain) fp16
__device__ __half  g_bufA[N_NODES * C];     // hs ping (hs = inv_out * h)
__device__ __half  g_bufB[N_NODES * C];     // hs pong
__device__ int     g_deg[2 * N_NODES];      // [0..N) deg_out, [N..2N) deg_in
__device__ float2  g_inv2[N_NODES];         // {inv_in, inv_out}
__device__ int     g_off[N_NODES + 1];
__device__ int     g_cursor[N_NODES];
__device__ int     g_csr_src[N_EDGES];      // src only, 4B/edge

// ============================================================
// 1) scores = x @ Wb + bb   [N, 40]
//    2 rows/thread, packed fma.rn.f32x2 accumulators, 3 CTAs/SM.
// ============================================================
#define GB_T 128
#define WKT  100

__global__ __launch_bounds__(GB_T, 3) void gemm_kernel(
    const float* __restrict__ x, const float* __restrict__ Wb,
    const float* __restrict__ bb, float* __restrict__ scores)
{
    __shared__ __align__(16) float Wt[WKT * C];
    __shared__ float bs[C];

    const int tid = threadIdx.x;
    if (tid < C) bs[tid] = bb[tid];

    const int r0 = blockIdx.x * 256 + tid;          // always < N (grid=391)
    const int r1 = r0 + 128;
    const size_t r1c = (r1 < N_NODES) ? (size_t)r1 : (size_t)(N_NODES - 1);
    const float4* xa_p = (const float4*)(x + (size_t)r0 * C_IN);
    const float4* xb_p = (const float4*)(x + r1c * C_IN);

    unsigned long long acc0[C / 2], acc1[C / 2];
#pragma unroll
    for (int j = 0; j < C / 2; j++) { acc0[j] = 0ull; acc1[j] = 0ull; }

#pragma unroll 1
    for (int t = 0; t < C_IN / WKT; t++) {          // 5 tiles of K=100
        __syncthreads();
        const float4* wsrc = (const float4*)(Wb + t * WKT * C);
        for (int i = tid; i < WKT * C / 4; i += GB_T)
            ((float4*)Wt)[i] = wsrc[i];
        __syncthreads();

#pragma unroll 1
        for (int kg = 0; kg < WKT / 4; kg++) {      // 25 groups of 4 k's
            const float4 xa = __ldg(xa_p + t * (WKT / 4) + kg);
            const float4 xb = __ldg(xb_p + t * (WKT / 4) + kg);
#pragma unroll
            for (int j = 0; j < 4; j++) {
                const float fa = j == 0 ? xa.x : j == 1 ? xa.y : j == 2 ? xa.z : xa.w;
                const float fb = j == 0 ? xb.x : j == 1 ? xb.y : j == 2 ? xb.z : xb.w;
                unsigned long long xa2, xb2;
                asm("mov.b64 %0, {%1, %1};" : "=l"(xa2) : "f"(fa));
                asm("mov.b64 %0, {%1, %1};" : "=l"(xb2) : "f"(fb));
                const ulonglong2* wr = (const ulonglong2*)(Wt + (kg * 4 + j) * C);
#pragma unroll
                for (int p = 0; p < C / 4; p++) {   // 10 LDS.128 = 20 pairs
                    const ulonglong2 w = wr[p];
                    asm("fma.rn.f32x2 %0, %1, %2, %0;" : "+l"(acc0[2*p  ]) : "l"(w.x), "l"(xa2));
                    asm("fma.rn.f32x2 %0, %1, %2, %0;" : "+l"(acc0[2*p+1]) : "l"(w.y), "l"(xa2));
                    asm("fma.rn.f32x2 %0, %1, %2, %0;" : "+l"(acc1[2*p  ]) : "l"(w.x), "l"(xb2));
                    asm("fma.rn.f32x2 %0, %1, %2, %0;" : "+l"(acc1[2*p+1]) : "l"(w.y), "l"(xb2));
                }
            }
        }
    }

    float o0[C], o1[C];
#pragma unroll
    for (int j = 0; j < C / 2; j++) {
        float lo, hi;
        asm("mov.b64 {%0, %1}, %2;" : "=f"(lo), "=f"(hi) : "l"(acc0[j]));
        o0[2*j] = lo + bs[2*j]; o0[2*j+1] = hi + bs[2*j+1];
        asm("mov.b64 {%0, %1}, %2;" : "=f"(lo), "=f"(hi) : "l"(acc1[j]));
        o1[2*j] = lo + bs[2*j]; o1[2*j+1] = hi + bs[2*j+1];
    }
    float4* d0 = (float4*)(scores + (size_t)r0 * C);
#pragma unroll
    for (int c4 = 0; c4 < C / 4; c4++)
        d0[c4] = make_float4(o0[c4*4], o0[c4*4+1], o0[c4*4+2], o0[c4*4+3]);
    if (r1 < N_NODES) {
        float4* d1 = (float4*)(scores + (size_t)r1 * C);
#pragma unroll
        for (int c4 = 0; c4 < C / 4; c4++)
            d1[c4] = make_float4(o1[c4*4], o1[c4*4+1], o1[c4*4+2], o1[c4*4+3]);
    }
}

// ============================================================
// 2) h0 = relu(softmax(scores)@W1+b1)@W2+b2
//    stores h0 (fp16) and hs0 = inv_out*h0 (fp16, into bufA)
// ============================================================
#define MLP_BS 128
__global__ __launch_bounds__(MLP_BS) void mlp_kernel(
    const float* __restrict__ scores,
    const float* __restrict__ W1, const float* __restrict__ b1,
    const float* __restrict__ W2, const float* __restrict__ b2)
{
    __shared__ float W1s[C * H];
    __shared__ float W2s[H * C];
    __shared__ float b1s[H];
    __shared__ float b2s[C];
    __shared__ float p_sh[C * MLP_BS];

    const int tid = threadIdx.x;
    for (int i = tid; i < C * H; i += MLP_BS) W1s[i] = W1[i];
    for (int i = tid; i < H * C; i += MLP_BS) W2s[i] = W2[i];
    if (tid < H) b1s[tid] = b1[tid];
    if (tid < C) b2s[tid] = b2[tid];
    __syncthreads();

    const int node = blockIdx.x * MLP_BS + tid;
    if (node >= N_NODES) return;

    const float4* sc4 = (const float4*)(scores + (size_t)node * C);
    float m = -1e30f;
#pragma unroll
    for (int q = 0; q < C / 4; q++) {
        const float4 v = sc4[q];
        p_sh[(q * 4 + 0) * MLP_BS + tid] = v.x;
        p_sh[(q * 4 + 1) * MLP_BS + tid] = v.y;
        p_sh[(q * 4 + 2) * MLP_BS + tid] = v.z;
        p_sh[(q * 4 + 3) * MLP_BS + tid] = v.w;
        m = fmaxf(m, fmaxf(fmaxf(v.x, v.y), fmaxf(v.z, v.w)));
    }
    float s = 0.f;
    for (int i = 0; i < C; i++) {
        const float e = __expf(p_sh[i * MLP_BS + tid] - m);
        p_sh[i * MLP_BS + tid] = e;
        s += e;
    }
    const float inv = 1.f / s;

    float h1[H];
#pragma unroll
    for (int j = 0; j < H; j++) h1[j] = b1s[j];
    for (int i = 0; i < C; i++) {
        const float pv = p_sh[i * MLP_BS + tid] * inv;
#pragma unroll
        for (int j = 0; j < H; j++) h1[j] += pv * W1s[i * H + j];
    }
#pragma unroll
    for (int j = 0; j < H; j++) h1[j] = fmaxf(h1[j], 0.f);

    float o[C];
    for (int c = 0; c < C; c++) {
        float a = b2s[c];
#pragma unroll
        for (int j = 0; j < H; j++) a += h1[j] * W2s[j * C + c];
        o[c] = a;
    }

    const float2 iv = __ldg(&g_inv2[node]);     // {inv_in, inv_out}
    uint4 pk_h[5], pk_s[5];
    uint32_t* ph = (uint32_t*)pk_h;
    uint32_t* ps = (uint32_t*)pk_s;
#pragma unroll
    for (int p = 0; p < C / 2; p++) {
        const __half2 hv = __floats2half2_rn(o[2*p], o[2*p+1]);
        ph[p] = *(const uint32_t*)&hv;
        const __half2 sv = __floats2half2_rn(o[2*p] * iv.y, o[2*p+1] * iv.y);
        ps[p] = *(const uint32_t*)&sv;
    }
    uint4* hr = (uint4*)(g_h0h + (size_t)node * C);
    uint4* sr = (uint4*)(g_bufA + (size_t)node * C);
#pragma unroll
    for (int p = 0; p < 5; p++) { hr[p] = pk_h[p]; sr[p] = pk_s[p]; }
}

// ============================================================
// 3) degrees (4 edges/thread, int4)
// ============================================================
__global__ void deg_kernel(const int4* __restrict__ src4, const int4* __restrict__ dst4)
{
    const int i = blockIdx.x * blockDim.x + threadIdx.x;
    if (i < N_EDGES / 4) {
        const int4 s = __ldg(src4 + i);
        const int4 d = __ldg(dst4 + i);
        atomicAdd(&g_deg[s.x], 1); atomicAdd(&g_deg[s.y], 1);
        atomicAdd(&g_deg[s.z], 1); atomicAdd(&g_deg[s.w], 1);
        atomicAdd(&g_deg[N_NODES + d.x], 1); atomicAdd(&g_deg[N_NODES + d.y], 1);
        atomicAdd(&g_deg[N_NODES + d.z], 1); atomicAdd(&g_deg[N_NODES + d.w], 1);
    }
}

// ============================================================
// 4) fused: inv-sqrt (packed float2) + exclusive scan -> off/cursor
// ============================================================
#define SCAN_T 1024
__global__ __launch_bounds__(SCAN_T) void scan_fused_kernel()
{
    __shared__ int part[SCAN_T];
    const int t = threadIdx.x;

    for (int i = t; i < N_NODES; i += SCAN_T) {
        const int d_o = g_deg[i];
        const int d_i = g_deg[N_NODES + i];
        g_inv2[i] = make_float2(d_i > 0 ? rsqrtf((float)d_i) : 0.f,
                                d_o > 0 ? rsqrtf((float)d_o) : 0.f);
    }

    const int CH = (N_NODES + SCAN_T - 1) / SCAN_T;
    const int base = t * CH;
    int s = 0;
    for (int i = 0; i < CH; i++) {
        const int idx = base + i;
        if (idx < N_NODES) s += g_deg[N_NODES + idx];
    }
    part[t] = s;
    __syncthreads();
    for (int o = 1; o < SCAN_T; o <<= 1) {
        const int v = (t >= o) ? part[t - o] : 0;
        __syncthreads();
        part[t] += v;
        __syncthreads();
    }
    int excl = part[t] - s;
    for (int i = 0; i < CH; i++) {
        const int idx = base + i;
        if (idx < N_NODES) {
            g_off[idx] = excl;
            g_cursor[idx] = excl;
            excl += g_deg[N_NODES + idx];
        }
    }
    if (t == SCAN_T - 1) g_off[N_NODES] = part[SCAN_T - 1];
}

// ============================================================
// 5) CSR fill: src only (4B scatter), 4 edges/thread
// ============================================================
__global__ void fill_csr_kernel(const int4* __restrict__ src4, const int4* __restrict__ dst4)
{
    const int i = blockIdx.x * blockDim.x + threadIdx.x;
    if (i < N_EDGES / 4) {
        const int4 s = __ldg(src4 + i);
        const int4 d = __ldg(dst4 + i);
        g_csr_src[atomicAdd(&g_cursor[d.x], 1)] = s.x;
        g_csr_src[atomicAdd(&g_cursor[d.y], 1)] = s.y;
        g_csr_src[atomicAdd(&g_cursor[d.z], 1)] = s.z;
        g_csr_src[atomicAdd(&g_cursor[d.w], 1)] = s.w;
    }
}

// ============================================================
// 6) one APPNP hop (R6-proven layout: 6 nodes/warp, 5 lanes/node,
//    uint4 = 8 halfs per lane). Unweighted gather of hs;
//    h_new = 0.9*inv_in*sum + 0.1*h0 ; hs_new = inv_out*h_new.
// ============================================================
#define HOP_BS 256
#define NPW 6                                // nodes per warp
#define NPB ((HOP_BS / 32) * NPW)            // 48 nodes per block

template <bool LAST>
__global__ __launch_bounds__(HOP_BS) void hop_kernel(
    const __half* __restrict__ hs_in,
    __half* __restrict__ hs_out, float* __restrict__ out_f)
{
    const int warp = threadIdx.x >> 5;
    const int lane = threadIdx.x & 31;
    const int sub = lane / 5;                // 0..5 active, lanes 30,31 idle
    const int q = lane - sub * 5;            // uint4 index within 80B row
    if (sub >= NPW) return;

    const int node = (blockIdx.x * (HOP_BS / 32) + warp) * NPW + sub;
    if (node >= N_NODES) return;

    const int beg = __ldg(&g_off[node]);
    const int end = __ldg(&g_off[node + 1]);

    float acc[8];
#pragma unroll
    for (int i = 0; i < 8; i++) acc[i] = 0.f;

#pragma unroll 4
    for (int e = beg; e < end; e++) {
        const int s = __ldg(&g_csr_src[e]);              // 4B broadcast
        const uint4 hv = __ldg((const uint4*)hs_in + (size_t)s * 5 + q);
        const __half2* hp = (const __half2*)&hv;
#pragma unroll
        for (int i = 0; i < 4; i++) {
            const float2 f = __half22float2(hp[i]);
            acc[2 * i + 0] += f.x;
            acc[2 * i + 1] += f.y;
        }
    }

    const float2 iv = __ldg(&g_inv2[node]);              // {inv_in, inv_out}
    const float w = (1.f - ALPHA) * iv.x;

    const uint4 h0v = __ldg((const uint4*)g_h0h + (size_t)node * 5 + q);
    const __half2* h0p = (const __half2*)&h0v;
    float o[8];
#pragma unroll
    for (int i = 0; i < 4; i++) {
        const float2 f = __half22float2(h0p[i]);
        o[2 * i + 0] = w * acc[2 * i + 0] + ALPHA * f.x;
        o[2 * i + 1] = w * acc[2 * i + 1] + ALPHA * f.y;
    }

    if (LAST) {
        float4* dst = (float4*)(out_f + (size_t)node * C + q * 8);
        dst[0] = make_float4(o[0], o[1], o[2], o[3]);
        dst[1] = make_float4(o[4], o[5], o[6], o[7]);
    } else {
        uint4 pk;
        uint32_t* pw = (uint32_t*)&pk;
#pragma unroll
        for (int i = 0; i < 4; i++) {
            const __half2 hv = __floats2half2_rn(o[2 * i] * iv.y, o[2 * i + 1] * iv.y);
            pw[i] = *(const uint32_t*)&hv;
        }
        ((uint4*)hs_out)[(size_t)node * 5 + q] = pk;
    }
}

// ============================================================
// launch
// ============================================================
extern "C" void kernel_launch(void* const* d_in, const int* in_sizes, int n_in,
                              void* d_out, int out_size)
{
    const float* x  = (const float*)d_in[0];
    const int*   ei = (const int*)d_in[1];
    const float* Wb = (const float*)d_in[2];
    const float* bb = (const float*)d_in[3];
    const float* W1 = (const float*)d_in[4];
    const float* b1 = (const float*)d_in[5];
    const float* W2 = (const float*)d_in[6];
    const float* b2 = (const float*)d_in[7];

    float* out = (float*)d_out;
    float* adjust = out;                              // [N, 40]
    float* scores = out + (size_t)N_NODES * C;        // [N, 40]

    const int4* src4 = (const int4*)ei;
    const int4* dst4 = (const int4*)(ei + N_EDGES);

    __half *Ap, *Bp;
    int *degp;
    cudaGetSymbolAddress((void**)&Ap, g_bufA);
    cudaGetSymbolAddress((void**)&Bp, g_bufB);
    cudaGetSymbolAddress((void**)&degp, g_deg);

    // order: memset(1), deg(2), scan(3), fill(4), gemm(5), mlp(6), hop0(7)...
    cudaMemsetAsync(degp, 0, 2 * N_NODES * sizeof(int), 0);

    const int e4blk = (N_EDGES / 4 + 255) / 256;
    deg_kernel<<<e4blk, 256>>>(src4, dst4);
    scan_fused_kernel<<<1, SCAN_T>>>();
    fill_csr_kernel<<<e4blk, 256>>>(src4, dst4);

    gemm_kernel<<<(N_NODES + 255) / 256, GB_T>>>(x, Wb, bb, scores);
    mlp_kernel<<<(N_NODES + MLP_BS - 1) / MLP_BS, MLP_BS>>>(scores, W1, b1, W2, b2);

    const int hop_grid = (N_NODES + NPB - 1) / NPB;
    const __half* hin = Ap;                           // hs0 written by mlp
    for (int k = 0; k < K_HOPS; k++) {
        if (k == K_HOPS - 1) {
            hop_kernel<true><<<hop_grid, HOP_BS>>>(hin, nullptr, adjust);
        } else {
            __half* o = (k % 2 == 0) ? Bp : Ap;       // first hop writes B
            hop_kernel<false><<<hop_grid, HOP_BS>>>(hin, o, nullptr);
            hin = o;
        }
    }
}

// round 9
// speedup vs baseline: 1.1842x; 1.0375x over previous
#include <cuda_runtime.h>
#include <cuda_fp16.h>
#include <cstdint>

// ---------------- problem constants ----------------
#define N_NODES 100000
#define N_EDGES 1600000
#define C_IN    500
#define C       40        // n_classes
#define H       64        // hidden
#define ALPHA   0.1f
#define K_HOPS  10

// ---------------- static scratch (no allocations allowed) ----------------
__device__ __half g_h0h[N_NODES * C];            // h0 (plain) fp16, 80B rows
// hs buffers padded to 128B rows (8 x uint4), first 5 uint4 = 40 halfs used
__device__ __align__(128) uint4 g_bufA[N_NODES * 8];
__device__ __align__(128) uint4 g_bufB[N_NODES * 8];
__device__ int     g_deg[2 * N_NODES];           // [0..N) out, [N..2N) in
__device__ float2  g_inv2[N_NODES];              // {inv_in, inv_out}
__device__ int     g_off[N_NODES + 1];
__device__ int     g_cursor[N_NODES];
__device__ int     g_csr_src[N_EDGES];           // src only, 4B/edge

// ============================================================
// 1) scores = x @ Wb + bb   [N, 40]
//    2 rows/thread, fma.rn.f32x2 accumulators, depth-1 x prefetch
//    (clamped index: no UB, last iteration re-loads same address).
// ============================================================
#define GB_T 128
#define WKT  100
#define KG   (WKT / 4)     // 25 float4 groups per tile

__global__ __launch_bounds__(GB_T, 3) void gemm_kernel(
    const float* __restrict__ x, const float* __restrict__ Wb,
    const float* __restrict__ bb, float* __restrict__ scores)
{
    __shared__ __align__(16) float Wt[WKT * C];
    __shared__ float bs[C];

    const int tid = threadIdx.x;
    if (tid < C) bs[tid] = bb[tid];

    const int r0 = blockIdx.x * 256 + tid;          // always < N (grid=391)
    const int r1 = r0 + 128;
    const size_t r1c = (r1 < N_NODES) ? (size_t)r1 : (size_t)(N_NODES - 1);
    const float4* xa_p = (const float4*)(x + (size_t)r0 * C_IN);
    const float4* xb_p = (const float4*)(x + r1c * C_IN);

    unsigned long long acc0[C / 2], acc1[C / 2];
#pragma unroll
    for (int j = 0; j < C / 2; j++) { acc0[j] = 0ull; acc1[j] = 0ull; }

#pragma unroll 1
    for (int t = 0; t < C_IN / WKT; t++) {          // 5 tiles of K=100
        __syncthreads();
        const float4* wsrc = (const float4*)(Wb + t * WKT * C);
        for (int i = tid; i < WKT * C / 4; i += GB_T)
            ((float4*)Wt)[i] = wsrc[i];
        __syncthreads();

        float4 xa = __ldg(xa_p + t * KG);
        float4 xb = __ldg(xb_p + t * KG);
#pragma unroll 1
        for (int kg = 0; kg < KG; kg++) {
            // prefetch next group (clamped: last iter reloads same addr, defined)
            const int nidx = (kg + 1 < KG) ? kg + 1 : kg;
            const float4 na = __ldg(xa_p + t * KG + nidx);
            const float4 nb = __ldg(xb_p + t * KG + nidx);
#pragma unroll
            for (int j = 0; j < 4; j++) {
                const float fa = j == 0 ? xa.x : j == 1 ? xa.y : j == 2 ? xa.z : xa.w;
                const float fb = j == 0 ? xb.x : j == 1 ? xb.y : j == 2 ? xb.z : xb.w;
                unsigned long long xa2, xb2;
                asm("mov.b64 %0, {%1, %1};" : "=l"(xa2) : "f"(fa));
                asm("mov.b64 %0, {%1, %1};" : "=l"(xb2) : "f"(fb));
                const ulonglong2* wr = (const ulonglong2*)(Wt + (kg * 4 + j) * C);
#pragma unroll
                for (int p = 0; p < C / 4; p++) {   // 10 LDS.128 = 20 pairs
                    const ulonglong2 w = wr[p];
                    asm("fma.rn.f32x2 %0, %1, %2, %0;" : "+l"(acc0[2*p  ]) : "l"(w.x), "l"(xa2));
                    asm("fma.rn.f32x2 %0, %1, %2, %0;" : "+l"(acc0[2*p+1]) : "l"(w.y), "l"(xa2));
                    asm("fma.rn.f32x2 %0, %1, %2, %0;" : "+l"(acc1[2*p  ]) : "l"(w.x), "l"(xb2));
                    asm("fma.rn.f32x2 %0, %1, %2, %0;" : "+l"(acc1[2*p+1]) : "l"(w.y), "l"(xb2));
                }
            }
            xa = na; xb = nb;
        }
    }

    float o0[C], o1[C];
#pragma unroll
    for (int j = 0; j < C / 2; j++) {
        float lo, hi;
        asm("mov.b64 {%0, %1}, %2;" : "=f"(lo), "=f"(hi) : "l"(acc0[j]));
        o0[2*j] = lo + bs[2*j]; o0[2*j+1] = hi + bs[2*j+1];
        asm("mov.b64 {%0, %1}, %2;" : "=f"(lo), "=f"(hi) : "l"(acc1[j]));
        o1[2*j] = lo + bs[2*j]; o1[2*j+1] = hi + bs[2*j+1];
    }
    float4* d0 = (float4*)(scores + (size_t)r0 * C);
#pragma unroll
    for (int c4 = 0; c4 < C / 4; c4++)
        d0[c4] = make_float4(o0[c4*4], o0[c4*4+1], o0[c4*4+2], o0[c4*4+3]);
    if (r1 < N_NODES) {
        float4* d1 = (float4*)(scores + (size_t)r1 * C);
#pragma unroll
        for (int c4 = 0; c4 < C / 4; c4++)
            d1[c4] = make_float4(o1[c4*4], o1[c4*4+1], o1[c4*4+2], o1[c4*4+3]);
    }
}

// ============================================================
// 2) h0 = relu(softmax(scores)@W1+b1)@W2+b2
//    stores h0 (fp16, 80B rows) and hs0 = inv_out*h0 (padded 128B rows)
// ============================================================
#define MLP_BS 128
__global__ __launch_bounds__(MLP_BS) void mlp_kernel(
    const float* __restrict__ scores,
    const float* __restrict__ W1, const float* __restrict__ b1,
    const float* __restrict__ W2, const float* __restrict__ b2)
{
    __shared__ float W1s[C * H];
    __shared__ float W2s[H * C];
    __shared__ float b1s[H];
    __shared__ float b2s[C];
    __shared__ float p_sh[C * MLP_BS];

    const int tid = threadIdx.x;
    for (int i = tid; i < C * H; i += MLP_BS) W1s[i] = W1[i];
    for (int i = tid; i < H * C; i += MLP_BS) W2s[i] = W2[i];
    if (tid < H) b1s[tid] = b1[tid];
    if (tid < C) b2s[tid] = b2[tid];
    __syncthreads();

    const int node = blockIdx.x * MLP_BS + tid;
    if (node >= N_NODES) return;

    const float4* sc4 = (const float4*)(scores + (size_t)node * C);
    float m = -1e30f;
#pragma unroll
    for (int q = 0; q < C / 4; q++) {
        const float4 v = sc4[q];
        p_sh[(q * 4 + 0) * MLP_BS + tid] = v.x;
        p_sh[(q * 4 + 1) * MLP_BS + tid] = v.y;
        p_sh[(q * 4 + 2) * MLP_BS + tid] = v.z;
        p_sh[(q * 4 + 3) * MLP_BS + tid] = v.w;
        m = fmaxf(m, fmaxf(fmaxf(v.x, v.y), fmaxf(v.z, v.w)));
    }
    float s = 0.f;
    for (int i = 0; i < C; i++) {
        const float e = __expf(p_sh[i * MLP_BS + tid] - m);
        p_sh[i * MLP_BS + tid] = e;
        s += e;
    }
    const float inv = 1.f / s;

    float h1[H];
#pragma unroll
    for (int j = 0; j < H; j++) h1[j] = b1s[j];
    for (int i = 0; i < C; i++) {
        const float pv = p_sh[i * MLP_BS + tid] * inv;
#pragma unroll
        for (int j = 0; j < H; j++) h1[j] += pv * W1s[i * H + j];
    }
#pragma unroll
    for (int j = 0; j < H; j++) h1[j] = fmaxf(h1[j], 0.f);

    float o[C];
    for (int c = 0; c < C; c++) {
        float a = b2s[c];
#pragma unroll
        for (int j = 0; j < H; j++) a += h1[j] * W2s[j * C + c];
        o[c] = a;
    }

    const float2 iv = __ldg(&g_inv2[node]);     // {inv_in, inv_out}
    uint4 pk_h[5], pk_s[5];
    uint32_t* ph = (uint32_t*)pk_h;
    uint32_t* ps = (uint32_t*)pk_s;
#pragma unroll
    for (int p = 0; p < C / 2; p++) {
        const __half2 hv = __floats2half2_rn(o[2*p], o[2*p+1]);
        ph[p] = *(const uint32_t*)&hv;
        const __half2 sv = __floats2half2_rn(o[2*p] * iv.y, o[2*p+1] * iv.y);
        ps[p] = *(const uint32_t*)&sv;
    }
    uint4* hr = (uint4*)(g_h0h + (size_t)node * C);
#pragma unroll
    for (int p = 0; p < 5; p++) hr[p] = pk_h[p];
    uint4* sr = g_bufA + (size_t)node * 8;      // padded 128B row
#pragma unroll
    for (int p = 0; p < 5; p++) sr[p] = pk_s[p];
}

// ============================================================
// 3) degrees (4 edges/thread, int4)
// ============================================================
__global__ void deg_kernel(const int4* __restrict__ src4, const int4* __restrict__ dst4)
{
    const int i = blockIdx.x * blockDim.x + threadIdx.x;
    if (i < N_EDGES / 4) {
        const int4 s = __ldg(src4 + i);
        const int4 d = __ldg(dst4 + i);
        atomicAdd(&g_deg[s.x], 1); atomicAdd(&g_deg[s.y], 1);
        atomicAdd(&g_deg[s.z], 1); atomicAdd(&g_deg[s.w], 1);
        atomicAdd(&g_deg[N_NODES + d.x], 1); atomicAdd(&g_deg[N_NODES + d.y], 1);
        atomicAdd(&g_deg[N_NODES + d.z], 1); atomicAdd(&g_deg[N_NODES + d.w], 1);
    }
}

// ============================================================
// 4) fused: inv-sqrt (packed float2) + exclusive scan -> off/cursor
// ============================================================
#define SCAN_T 1024
__global__ __launch_bounds__(SCAN_T) void scan_fused_kernel()
{
    __shared__ int part[SCAN_T];
    const int t = threadIdx.x;

    for (int i = t; i < N_NODES; i += SCAN_T) {
        const int d_o = g_deg[i];
        const int d_i = g_deg[N_NODES + i];
        g_inv2[i] = make_float2(d_i > 0 ? rsqrtf((float)d_i) : 0.f,
                                d_o > 0 ? rsqrtf((float)d_o) : 0.f);
    }

    const int CH = (N_NODES + SCAN_T - 1) / SCAN_T;
    const int base = t * CH;
    int s = 0;
    for (int i = 0; i < CH; i++) {
        const int idx = base + i;
        if (idx < N_NODES) s += g_deg[N_NODES + idx];
    }
    part[t] = s;
    __syncthreads();
    for (int o = 1; o < SCAN_T; o <<= 1) {
        const int v = (t >= o) ? part[t - o] : 0;
        __syncthreads();
        part[t] += v;
        __syncthreads();
    }
    int excl = part[t] - s;
    for (int i = 0; i < CH; i++) {
        const int idx = base + i;
        if (idx < N_NODES) {
            g_off[idx] = excl;
            g_cursor[idx] = excl;
            excl += g_deg[N_NODES + idx];
        }
    }
    if (t == SCAN_T - 1) g_off[N_NODES] = part[SCAN_T - 1];
}

// ============================================================
// 5) CSR fill: src only (4B scatter), 4 edges/thread
// ============================================================
__global__ void fill_csr_kernel(const int4* __restrict__ src4, const int4* __restrict__ dst4)
{
    const int i = blockIdx.x * blockDim.x + threadIdx.x;
    if (i < N_EDGES / 4) {
        const int4 s = __ldg(src4 + i);
        const int4 d = __ldg(dst4 + i);
        g_csr_src[atomicAdd(&g_cursor[d.x], 1)] = s.x;
        g_csr_src[atomicAdd(&g_cursor[d.y], 1)] = s.y;
        g_csr_src[atomicAdd(&g_cursor[d.z], 1)] = s.z;
        g_csr_src[atomicAdd(&g_cursor[d.w], 1)] = s.w;
    }
}

// ============================================================
// 6) one APPNP hop: 6 nodes/warp, 5 lanes/node, uint4/lane.
//    hs rows PADDED to 128B -> each node's gather = one cache line.
//    h_new = 0.9*inv_in*sum + 0.1*h0 ; hs_new = inv_out*h_new.
// ============================================================
#define HOP_BS 256
#define NPW 6
#define NPB ((HOP_BS / 32) * NPW)            // 48 nodes per block

template <bool LAST>
__global__ __launch_bounds__(HOP_BS) void hop_kernel(
    const uint4* __restrict__ hs_in,
    uint4* __restrict__ hs_out, float* __restrict__ out_f)
{
    const int warp = threadIdx.x >> 5;
    const int lane = threadIdx.x & 31;
    const int sub = lane / 5;                // 0..5 active, lanes 30,31 idle
    const int q = lane - sub * 5;            // uint4 index within row
    if (sub >= NPW) return;

    const int node = (blockIdx.x * (HOP_BS / 32) + warp) * NPW + sub;
    if (node >= N_NODES) return;

    const int beg = __ldg(&g_off[node]);
    const int end = __ldg(&g_off[node + 1]);

    float acc[8];
#pragma unroll
    for (int i = 0; i < 8; i++) acc[i] = 0.f;

#pragma unroll 4
    for (int e = beg; e < end; e++) {
        const int s = __ldg(&g_csr_src[e]);              // 4B broadcast
        const uint4 hv = __ldg(hs_in + (size_t)s * 8 + q);   // 128B rows
        const __half2* hp = (const __half2*)&hv;
#pragma unroll
        for (int i = 0; i < 4; i++) {
            const float2 f = __half22float2(hp[i]);
            acc[2 * i + 0] += f.x;
            acc[2 * i + 1] += f.y;
        }
    }

    const float2 iv = __ldg(&g_inv2[node]);              // {inv_in, inv_out}
    const float w = (1.f - ALPHA) * iv.x;

    const uint4 h0v = __ldg((const uint4*)g_h0h + (size_t)node * 5 + q);
    const __half2* h0p = (const __half2*)&h0v;
    float o[8];
#pragma unroll
    for (int i = 0; i < 4; i++) {
        const float2 f = __half22float2(h0p[i]);
        o[2 * i + 0] = w * acc[2 * i + 0] + ALPHA * f.x;
        o[2 * i + 1] = w * acc[2 * i + 1] + ALPHA * f.y;
    }

    if (LAST) {
        float4* dst = (float4*)(out_f + (size_t)node * C + q * 8);
        dst[0] = make_float4(o[0], o[1], o[2], o[3]);
        dst[1] = make_float4(o[4], o[5], o[6], o[7]);
    } else {
        uint4 pk;
        uint32_t* pw = (uint32_t*)&pk;
#pragma unroll
        for (int i = 0; i < 4; i++) {
            const __half2 hv = __floats2half2_rn(o[2 * i] * iv.y, o[2 * i + 1] * iv.y);
            pw[i] = *(const uint32_t*)&hv;
        }
        hs_out[(size_t)node * 8 + q] = pk;
    }
}

// ============================================================
// launch
// ============================================================
extern "C" void kernel_launch(void* const* d_in, const int* in_sizes, int n_in,
                              void* d_out, int out_size)
{
    const float* x  = (const float*)d_in[0];
    const int*   ei = (const int*)d_in[1];
    const float* Wb = (const float*)d_in[2];
    const float* bb = (const float*)d_in[3];
    const float* W1 = (const float*)d_in[4];
    const float* b1 = (const float*)d_in[5];
    const float* W2 = (const float*)d_in[6];
    const float* b2 = (const float*)d_in[7];

    float* out = (float*)d_out;
    float* adjust = out;                              // [N, 40]
    float* scores = out + (size_t)N_NODES * C;        // [N, 40]

    const int4* src4 = (const int4*)ei;
    const int4* dst4 = (const int4*)(ei + N_EDGES);

    uint4 *Ap, *Bp;
    int *degp;
    cudaGetSymbolAddress((void**)&Ap, g_bufA);
    cudaGetSymbolAddress((void**)&Bp, g_bufB);
    cudaGetSymbolAddress((void**)&degp, g_deg);

    cudaMemsetAsync(degp, 0, 2 * N_NODES * sizeof(int), 0);

    const int e4blk = (N_EDGES / 4 + 255) / 256;
    deg_kernel<<<e4blk, 256>>>(src4, dst4);
    scan_fused_kernel<<<1, SCAN_T>>>();
    fill_csr_kernel<<<e4blk, 256>>>(src4, dst4);

    gemm_kernel<<<(N_NODES + 255) / 256, GB_T>>>(x, Wb, bb, scores);
    mlp_kernel<<<(N_NODES + MLP_BS - 1) / MLP_BS, MLP_BS>>>(scores, W1, b1, W2, b2);

    const int hop_grid = (N_NODES + NPB - 1) / NPB;
    const uint4* hin = Ap;                            // hs0 written by mlp
    for (int k = 0; k < K_HOPS; k++) {
        if (k == K_HOPS - 1) {
            hop_kernel<true><<<hop_grid, HOP_BS>>>(hin, nullptr, adjust);
        } else {
            uint4* o = (k % 2 == 0) ? Bp : Ap;        // first hop writes B
            hop_kernel<false><<<hop_grid, HOP_BS>>>(hin, o, nullptr);
            hin = o;
        }
    }
}

// round 10
// speedup vs baseline: 1.5351x; 1.2963x over previous
#include <cuda_runtime.h>
#include <cuda_fp16.h>
#include <cstdint>

// ---------------- problem constants ----------------
#define N_NODES 100000
#define N_EDGES 1600000
#define C_IN    500
#define C       40        // n_classes
#define H       64        // hidden
#define ALPHA   0.1f
#define K_HOPS  10
#define NBLK    391       // ceil(N_NODES/256)
#define BINS    64

// ---------------- static scratch (no allocations allowed) ----------------
__device__ __half g_h0h[N_NODES * C];            // h0 (plain) fp16, 80B rows
// hs buffers padded to 128B rows (8 x uint4), first 5 uint4 = 40 halfs used
__device__ __align__(128) uint4 g_bufA[N_NODES * 8];
__device__ __align__(128) uint4 g_bufB[N_NODES * 8];
// [0..N) deg_out, [N..2N) deg_in, [2N..2N+64) bin counts, [2N+64..2N+128) bin cursors
__device__ int     g_deg[2 * N_NODES + 2 * BINS];
__device__ float2  g_inv2[N_NODES];              // {inv_in, inv_out}
__device__ int     g_off[N_NODES + 1];
__device__ int     g_cursor[N_NODES];
__device__ int     g_csr_src[N_EDGES];           // src only, 4B/edge
__device__ int     g_perm[N_NODES];              // degree-sorted node order
__device__ int     g_part[512];
__device__ int     g_base[512];

// ============================================================
// 1) scores = x @ Wb + bb   [N, 40]  (unchanged from R9)
// ============================================================
#define GB_T 128
#define WKT  100
#define KG   (WKT / 4)

__global__ __launch_bounds__(GB_T, 3) void gemm_kernel(
    const float* __restrict__ x, const float* __restrict__ Wb,
    const float* __restrict__ bb, float* __restrict__ scores)
{
    __shared__ __align__(16) float Wt[WKT * C];
    __shared__ float bs[C];

    const int tid = threadIdx.x;
    if (tid < C) bs[tid] = bb[tid];

    const int r0 = blockIdx.x * 256 + tid;
    const int r1 = r0 + 128;
    const size_t r1c = (r1 < N_NODES) ? (size_t)r1 : (size_t)(N_NODES - 1);
    const float4* xa_p = (const float4*)(x + (size_t)r0 * C_IN);
    const float4* xb_p = (const float4*)(x + r1c * C_IN);

    unsigned long long acc0[C / 2], acc1[C / 2];
#pragma unroll
    for (int j = 0; j < C / 2; j++) { acc0[j] = 0ull; acc1[j] = 0ull; }

#pragma unroll 1
    for (int t = 0; t < C_IN / WKT; t++) {
        __syncthreads();
        const float4* wsrc = (const float4*)(Wb + t * WKT * C);
        for (int i = tid; i < WKT * C / 4; i += GB_T)
            ((float4*)Wt)[i] = wsrc[i];
        __syncthreads();

        float4 xa = __ldg(xa_p + t * KG);
        float4 xb = __ldg(xb_p + t * KG);
#pragma unroll 1
        for (int kg = 0; kg < KG; kg++) {
            const int nidx = (kg + 1 < KG) ? kg + 1 : kg;
            const float4 na = __ldg(xa_p + t * KG + nidx);
            const float4 nb = __ldg(xb_p + t * KG + nidx);
#pragma unroll
            for (int j = 0; j < 4; j++) {
                const float fa = j == 0 ? xa.x : j == 1 ? xa.y : j == 2 ? xa.z : xa.w;
                const float fb = j == 0 ? xb.x : j == 1 ? xb.y : j == 2 ? xb.z : xb.w;
                unsigned long long xa2, xb2;
                asm("mov.b64 %0, {%1, %1};" : "=l"(xa2) : "f"(fa));
                asm("mov.b64 %0, {%1, %1};" : "=l"(xb2) : "f"(fb));
                const ulonglong2* wr = (const ulonglong2*)(Wt + (kg * 4 + j) * C);
#pragma unroll
                for (int p = 0; p < C / 4; p++) {
                    const ulonglong2 w = wr[p];
                    asm("fma.rn.f32x2 %0, %1, %2, %0;" : "+l"(acc0[2*p  ]) : "l"(w.x), "l"(xa2));
                    asm("fma.rn.f32x2 %0, %1, %2, %0;" : "+l"(acc0[2*p+1]) : "l"(w.y), "l"(xa2));
                    asm("fma.rn.f32x2 %0, %1, %2, %0;" : "+l"(acc1[2*p  ]) : "l"(w.x), "l"(xb2));
                    asm("fma.rn.f32x2 %0, %1, %2, %0;" : "+l"(acc1[2*p+1]) : "l"(w.y), "l"(xb2));
                }
            }
            xa = na; xb = nb;
        }
    }

    float o0[C], o1[C];
#pragma unroll
    for (int j = 0; j < C / 2; j++) {
        float lo, hi;
        asm("mov.b64 {%0, %1}, %2;" : "=f"(lo), "=f"(hi) : "l"(acc0[j]));
        o0[2*j] = lo + bs[2*j]; o0[2*j+1] = hi + bs[2*j+1];
        asm("mov.b64 {%0, %1}, %2;" : "=f"(lo), "=f"(hi) : "l"(acc1[j]));
        o1[2*j] = lo + bs[2*j]; o1[2*j+1] = hi + bs[2*j+1];
    }
    float4* d0 = (float4*)(scores + (size_t)r0 * C);
#pragma unroll
    for (int c4 = 0; c4 < C / 4; c4++)
        d0[c4] = make_float4(o0[c4*4], o0[c4*4+1], o0[c4*4+2], o0[c4*4+3]);
    if (r1 < N_NODES) {
        float4* d1 = (float4*)(scores + (size_t)r1 * C);
#pragma unroll
        for (int c4 = 0; c4 < C / 4; c4++)
            d1[c4] = make_float4(o1[c4*4], o1[c4*4+1], o1[c4*4+2], o1[c4*4+3]);
    }
}

// ============================================================
// 2) MLP -> h0 (fp16) + hs0 = inv_out*h0 (padded rows)
// ============================================================
#define MLP_BS 128
__global__ __launch_bounds__(MLP_BS) void mlp_kernel(
    const float* __restrict__ scores,
    const float* __restrict__ W1, const float* __restrict__ b1,
    const float* __restrict__ W2, const float* __restrict__ b2)
{
    __shared__ float W1s[C * H];
    __shared__ float W2s[H * C];
    __shared__ float b1s[H];
    __shared__ float b2s[C];
    __shared__ float p_sh[C * MLP_BS];

    const int tid = threadIdx.x;
    for (int i = tid; i < C * H; i += MLP_BS) W1s[i] = W1[i];
    for (int i = tid; i < H * C; i += MLP_BS) W2s[i] = W2[i];
    if (tid < H) b1s[tid] = b1[tid];
    if (tid < C) b2s[tid] = b2[tid];
    __syncthreads();

    const int node = blockIdx.x * MLP_BS + tid;
    if (node >= N_NODES) return;

    const float4* sc4 = (const float4*)(scores + (size_t)node * C);
    float m = -1e30f;
#pragma unroll
    for (int q = 0; q < C / 4; q++) {
        const float4 v = sc4[q];
        p_sh[(q * 4 + 0) * MLP_BS + tid] = v.x;
        p_sh[(q * 4 + 1) * MLP_BS + tid] = v.y;
        p_sh[(q * 4 + 2) * MLP_BS + tid] = v.z;
        p_sh[(q * 4 + 3) * MLP_BS + tid] = v.w;
        m = fmaxf(m, fmaxf(fmaxf(v.x, v.y), fmaxf(v.z, v.w)));
    }
    float s = 0.f;
    for (int i = 0; i < C; i++) {
        const float e = __expf(p_sh[i * MLP_BS + tid] - m);
        p_sh[i * MLP_BS + tid] = e;
        s += e;
    }
    const float inv = 1.f / s;

    float h1[H];
#pragma unroll
    for (int j = 0; j < H; j++) h1[j] = b1s[j];
    for (int i = 0; i < C; i++) {
        const float pv = p_sh[i * MLP_BS + tid] * inv;
#pragma unroll
        for (int j = 0; j < H; j++) h1[j] += pv * W1s[i * H + j];
    }
#pragma unroll
    for (int j = 0; j < H; j++) h1[j] = fmaxf(h1[j], 0.f);

    float o[C];
    for (int c = 0; c < C; c++) {
        float a = b2s[c];
#pragma unroll
        for (int j = 0; j < H; j++) a += h1[j] * W2s[j * C + c];
        o[c] = a;
    }

    const float2 iv = __ldg(&g_inv2[node]);
    uint4 pk_h[5], pk_s[5];
    uint32_t* ph = (uint32_t*)pk_h;
    uint32_t* ps = (uint32_t*)pk_s;
#pragma unroll
    for (int p = 0; p < C / 2; p++) {
        const __half2 hv = __floats2half2_rn(o[2*p], o[2*p+1]);
        ph[p] = *(const uint32_t*)&hv;
        const __half2 sv = __floats2half2_rn(o[2*p] * iv.y, o[2*p+1] * iv.y);
        ps[p] = *(const uint32_t*)&sv;
    }
    uint4* hr = (uint4*)(g_h0h + (size_t)node * C);
#pragma unroll
    for (int p = 0; p < 5; p++) hr[p] = pk_h[p];
    uint4* sr = g_bufA + (size_t)node * 8;
#pragma unroll
    for (int p = 0; p < 5; p++) sr[p] = pk_s[p];
}

// ============================================================
// 3) degrees (4 edges/thread, int4)
// ============================================================
__global__ void deg_kernel(const int4* __restrict__ src4, const int4* __restrict__ dst4)
{
    const int i = blockIdx.x * blockDim.x + threadIdx.x;
    if (i < N_EDGES / 4) {
        const int4 s = __ldg(src4 + i);
        const int4 d = __ldg(dst4 + i);
        atomicAdd(&g_deg[s.x], 1); atomicAdd(&g_deg[s.y], 1);
        atomicAdd(&g_deg[s.z], 1); atomicAdd(&g_deg[s.w], 1);
        atomicAdd(&g_deg[N_NODES + d.x], 1); atomicAdd(&g_deg[N_NODES + d.y], 1);
        atomicAdd(&g_deg[N_NODES + d.z], 1); atomicAdd(&g_deg[N_NODES + d.w], 1);
    }
}

// ============================================================
// 4) inv-sqrt -> packed float2 {inv_in, inv_out}
// ============================================================
__global__ void invsqrt_kernel()
{
    const int i = blockIdx.x * blockDim.x + threadIdx.x;
    if (i < N_NODES) {
        const int d_o = g_deg[i];
        const int d_i = g_deg[N_NODES + i];
        g_inv2[i] = make_float2(d_i > 0 ? rsqrtf((float)d_i) : 0.f,
                                d_o > 0 ? rsqrtf((float)d_o) : 0.f);
    }
}

// ============================================================
// 5) 3-phase parallel exclusive scan of deg_in -> g_off, g_cursor
// ============================================================
__global__ __launch_bounds__(256) void scan1_kernel()
{
    __shared__ int red[256];
    const int node = blockIdx.x * 256 + threadIdx.x;
    const int v = (node < N_NODES) ? g_deg[N_NODES + node] : 0;
    red[threadIdx.x] = v;
    __syncthreads();
#pragma unroll
    for (int o = 128; o > 0; o >>= 1) {
        if (threadIdx.x < o) red[threadIdx.x] += red[threadIdx.x + o];
        __syncthreads();
    }
    if (threadIdx.x == 0) g_part[blockIdx.x] = red[0];
}

__global__ __launch_bounds__(512) void scan2_kernel()
{
    __shared__ int sm[512];
    const int t = threadIdx.x;
    const int v = (t < NBLK) ? g_part[t] : 0;
    sm[t] = v;
    __syncthreads();
#pragma unroll
    for (int o = 1; o < 512; o <<= 1) {
        const int u = (t >= o) ? sm[t - o] : 0;
        __syncthreads();
        sm[t] += u;
        __syncthreads();
    }
    if (t < NBLK) g_base[t] = sm[t] - v;          // exclusive base per block
    if (t == 511) g_off[N_NODES] = sm[511];       // total = N_EDGES
}

__global__ __launch_bounds__(256) void scan3_kernel()
{
    __shared__ int sm[256];
    const int node = blockIdx.x * 256 + threadIdx.x;
    const int v = (node < N_NODES) ? g_deg[N_NODES + node] : 0;
    sm[threadIdx.x] = v;
    __syncthreads();
#pragma unroll
    for (int o = 1; o < 256; o <<= 1) {
        const int u = (threadIdx.x >= o) ? sm[threadIdx.x - o] : 0;
        __syncthreads();
        sm[threadIdx.x] += u;
        __syncthreads();
    }
    if (node < N_NODES) {
        const int off = g_base[blockIdx.x] + sm[threadIdx.x] - v;
        g_off[node] = off;
        g_cursor[node] = off;
    }
}

// ============================================================
// 6) counting sort of nodes by deg_in (64 bins) -> g_perm
// ============================================================
__global__ void hist_kernel()
{
    const int i = blockIdx.x * blockDim.x + threadIdx.x;
    if (i < N_NODES) {
        const int d = min(g_deg[N_NODES + i], BINS - 1);
        atomicAdd(&g_deg[2 * N_NODES + d], 1);
    }
}

__global__ __launch_bounds__(BINS) void binscan_kernel()
{
    __shared__ int sm[BINS];
    const int t = threadIdx.x;
    const int v = g_deg[2 * N_NODES + t];
    sm[t] = v;
    __syncthreads();
#pragma unroll
    for (int o = 1; o < BINS; o <<= 1) {
        const int u = (t >= o) ? sm[t - o] : 0;
        __syncthreads();
        sm[t] += u;
        __syncthreads();
    }
    g_deg[2 * N_NODES + BINS + t] = sm[t] - v;    // exclusive -> bin cursor
}

__global__ void scatter_kernel()
{
    const int i = blockIdx.x * blockDim.x + threadIdx.x;
    if (i < N_NODES) {
        const int d = min(g_deg[N_NODES + i], BINS - 1);
        const int pos = atomicAdd(&g_deg[2 * N_NODES + BINS + d], 1);
        g_perm[pos] = i;
    }
}

// ============================================================
// 7) CSR fill: src only (4B scatter), 4 edges/thread
// ============================================================
__global__ void fill_csr_kernel(const int4* __restrict__ src4, const int4* __restrict__ dst4)
{
    const int i = blockIdx.x * blockDim.x + threadIdx.x;
    if (i < N_EDGES / 4) {
        const int4 s = __ldg(src4 + i);
        const int4 d = __ldg(dst4 + i);
        g_csr_src[atomicAdd(&g_cursor[d.x], 1)] = s.x;
        g_csr_src[atomicAdd(&g_cursor[d.y], 1)] = s.y;
        g_csr_src[atomicAdd(&g_cursor[d.z], 1)] = s.z;
        g_csr_src[atomicAdd(&g_cursor[d.w], 1)] = s.w;
    }
}

// ============================================================
// 8) one APPNP hop: 6 nodes/warp, 5 lanes/node, uint4/lane.
//    Nodes taken in degree-sorted order (g_perm) so all 6 nodes
//    in a warp have ~equal degree -> trip count ~ mean not max.
// ============================================================
#define HOP_BS 256
#define NPW 6
#define NPB ((HOP_BS / 32) * NPW)            // 48 nodes per block

template <bool LAST>
__global__ __launch_bounds__(HOP_BS) void hop_kernel(
    const uint4* __restrict__ hs_in,
    uint4* __restrict__ hs_out, float* __restrict__ out_f)
{
    const int warp = threadIdx.x >> 5;
    const int lane = threadIdx.x & 31;
    const int sub = lane / 5;                // 0..5 active, lanes 30,31 idle
    const int q = lane - sub * 5;            // uint4 index within row
    if (sub >= NPW) return;

    const int idx = (blockIdx.x * (HOP_BS / 32) + warp) * NPW + sub;
    if (idx >= N_NODES) return;
    const int node = __ldg(&g_perm[idx]);

    const int beg = __ldg(&g_off[node]);
    const int end = __ldg(&g_off[node + 1]);

    float acc[8];
#pragma unroll
    for (int i = 0; i < 8; i++) acc[i] = 0.f;

#pragma unroll 4
    for (int e = beg; e < end; e++) {
        const int s = __ldg(&g_csr_src[e]);
        const uint4 hv = __ldg(hs_in + (size_t)s * 8 + q);   // 128B rows
        const __half2* hp = (const __half2*)&hv;
#pragma unroll
        for (int i = 0; i < 4; i++) {
            const float2 f = __half22float2(hp[i]);
            acc[2 * i + 0] += f.x;
            acc[2 * i + 1] += f.y;
        }
    }

    const float2 iv = __ldg(&g_inv2[node]);              // {inv_in, inv_out}
    const float w = (1.f - ALPHA) * iv.x;

    const uint4 h0v = __ldg((const uint4*)g_h0h + (size_t)node * 5 + q);
    const __half2* h0p = (const __half2*)&h0v;
    float o[8];
#pragma unroll
    for (int i = 0; i < 4; i++) {
        const float2 f = __half22float2(h0p[i]);
        o[2 * i + 0] = w * acc[2 * i + 0] + ALPHA * f.x;
        o[2 * i + 1] = w * acc[2 * i + 1] + ALPHA * f.y;
    }

    if (LAST) {
        float4* dst = (float4*)(out_f + (size_t)node * C + q * 8);
        dst[0] = make_float4(o[0], o[1], o[2], o[3]);
        dst[1] = make_float4(o[4], o[5], o[6], o[7]);
    } else {
        uint4 pk;
        uint32_t* pw = (uint32_t*)&pk;
#pragma unroll
        for (int i = 0; i < 4; i++) {
            const __half2 hv = __floats2half2_rn(o[2 * i] * iv.y, o[2 * i + 1] * iv.y);
            pw[i] = *(const uint32_t*)&hv;
        }
        hs_out[(size_t)node * 8 + q] = pk;
    }
}

// ============================================================
// launch
// ============================================================
extern "C" void kernel_launch(void* const* d_in, const int* in_sizes, int n_in,
                              void* d_out, int out_size)
{
    const float* x  = (const float*)d_in[0];
    const int*   ei = (const int*)d_in[1];
    const float* Wb = (const float*)d_in[2];
    const float* bb = (const float*)d_in[3];
    const float* W1 = (const float*)d_in[4];
    const float* b1 = (const float*)d_in[5];
    const float* W2 = (const float*)d_in[6];
    const float* b2 = (const float*)d_in[7];

    float* out = (float*)d_out;
    float* adjust = out;                              // [N, 40]
    float* scores = out + (size_t)N_NODES * C;        // [N, 40]

    const int4* src4 = (const int4*)ei;
    const int4* dst4 = (const int4*)(ei + N_EDGES);

    uint4 *Ap, *Bp;
    int *degp;
    cudaGetSymbolAddress((void**)&Ap, g_bufA);
    cudaGetSymbolAddress((void**)&Bp, g_bufB);
    cudaGetSymbolAddress((void**)&degp, g_deg);

    // zero degrees + bin counts + bin cursors in one memset
    cudaMemsetAsync(degp, 0, (2 * N_NODES + 2 * BINS) * sizeof(int), 0);

    const int e4blk = (N_EDGES / 4 + 255) / 256;
    const int nblk  = (N_NODES + 255) / 256;

    deg_kernel<<<e4blk, 256>>>(src4, dst4);
    invsqrt_kernel<<<nblk, 256>>>();
    scan1_kernel<<<NBLK, 256>>>();
    scan2_kernel<<<1, 512>>>();
    scan3_kernel<<<NBLK, 256>>>();
    hist_kernel<<<nblk, 256>>>();
    binscan_kernel<<<1, BINS>>>();
    scatter_kernel<<<nblk, 256>>>();
    fill_csr_kernel<<<e4blk, 256>>>(src4, dst4);

    gemm_kernel<<<(N_NODES + 255) / 256, GB_T>>>(x, Wb, bb, scores);
    mlp_kernel<<<(N_NODES + MLP_BS - 1) / MLP_BS, MLP_BS>>>(scores, W1, b1, W2, b2);

    const int hop_grid = (N_NODES + NPB - 1) / NPB;
    const uint4* hin = Ap;                            // hs0 written by mlp
    for (int k = 0; k < K_HOPS; k++) {
        if (k == K_HOPS - 1) {
            hop_kernel<true><<<hop_grid, HOP_BS>>>(hin, nullptr, adjust);
        } else {
            uint4* o = (k % 2 == 0) ? Bp : Ap;        // first hop writes B
            hop_kernel<false><<<hop_grid, HOP_BS>>>(hin, o, nullptr);
            hin = o;
        }
    }
}

// round 11
// speedup vs baseline: 1.5476x; 1.0081x over previous
#include <cuda_runtime.h>
#include <cuda_fp16.h>
#include <cstdint>

// ---------------- problem constants ----------------
#define N_NODES 100000
#define N_EDGES 1600000
#define C_IN    500
#define C       40        // n_classes
#define H       64        // hidden
#define ALPHA   0.1f
#define K_HOPS  10
#define NBLK    391       // ceil(N_NODES/256)
#define BINS    64
#define CSR_CAP (N_EDGES + 3 * N_NODES)   // padded CSR capacity (1.9M, %4==0)

// ---------------- static scratch (no allocations allowed) ----------------
__device__ __half g_h0h[N_NODES * C];            // h0 (plain) fp16, 80B rows
// hs buffers: N_NODES+1 rows of 128B; row N_NODES is the SENTINEL ZERO ROW
// (zero-initialized device globals; never written -> stays zero forever)
__device__ __align__(128) uint4 g_bufA[(N_NODES + 1) * 8];
__device__ __align__(128) uint4 g_bufB[(N_NODES + 1) * 8];
// [0..N) deg_out, [N..2N) deg_in, [2N..2N+64) bin counts, [2N+64..2N+128) bin cursors
__device__ int     g_deg[2 * N_NODES + 2 * BINS];
__device__ float2  g_inv2[N_NODES];              // {inv_in, inv_out}
__device__ int     g_off[N_NODES + 1];           // PADDED offsets (%4==0)
__device__ int     g_cursor[N_NODES];
__device__ int     g_csr_src[CSR_CAP];           // src only; pad slots = N_NODES
__device__ int     g_perm[N_NODES];              // degree-sorted node order
__device__ int     g_part[512];
__device__ int     g_base[512];

// ============================================================
// 1) scores = x @ Wb + bb   [N, 40]
//    3 rows/thread, fma.rn.f32x2 accumulators, depth-1 x prefetch.
// ============================================================
#define GB_T 128
#define WKT  100
#define KG   (WKT / 4)
#define ROWS3 (3 * GB_T)   // 384 rows per block

__global__ __launch_bounds__(GB_T, 2) void gemm_kernel(
    const float* __restrict__ x, const float* __restrict__ Wb,
    const float* __restrict__ bb, float* __restrict__ scores)
{
    __shared__ __align__(16) float Wt[WKT * C];
    __shared__ float bs[C];

    const int tid = threadIdx.x;
    if (tid < C) bs[tid] = bb[tid];

    const int r0 = blockIdx.x * ROWS3 + tid;        // always < N (grid=261)
    const int r1 = r0 + GB_T;
    const int r2 = r0 + 2 * GB_T;
    const size_t r1c = (r1 < N_NODES) ? (size_t)r1 : (size_t)(N_NODES - 1);
    const size_t r2c = (r2 < N_NODES) ? (size_t)r2 : (size_t)(N_NODES - 1);
    const float4* xa_p = (const float4*)(x + (size_t)r0 * C_IN);
    const float4* xb_p = (const float4*)(x + r1c * C_IN);
    const float4* xc_p = (const float4*)(x + r2c * C_IN);

    unsigned long long acc0[C / 2], acc1[C / 2], acc2[C / 2];
#pragma unroll
    for (int j = 0; j < C / 2; j++) { acc0[j] = 0ull; acc1[j] = 0ull; acc2[j] = 0ull; }

#pragma unroll 1
    for (int t = 0; t < C_IN / WKT; t++) {
        __syncthreads();
        const float4* wsrc = (const float4*)(Wb + t * WKT * C);
        for (int i = tid; i < WKT * C / 4; i += GB_T)
            ((float4*)Wt)[i] = wsrc[i];
        __syncthreads();

        float4 xa = __ldg(xa_p + t * KG);
        float4 xb = __ldg(xb_p + t * KG);
        float4 xc = __ldg(xc_p + t * KG);
#pragma unroll 1
        for (int kg = 0; kg < KG; kg++) {
            const int nidx = (kg + 1 < KG) ? kg + 1 : kg;
            const float4 na = __ldg(xa_p + t * KG + nidx);
            const float4 nb = __ldg(xb_p + t * KG + nidx);
            const float4 nc = __ldg(xc_p + t * KG + nidx);
#pragma unroll
            for (int j = 0; j < 4; j++) {
                const float fa = j == 0 ? xa.x : j == 1 ? xa.y : j == 2 ? xa.z : xa.w;
                const float fb = j == 0 ? xb.x : j == 1 ? xb.y : j == 2 ? xb.z : xb.w;
                const float fc = j == 0 ? xc.x : j == 1 ? xc.y : j == 2 ? xc.z : xc.w;
                unsigned long long xa2, xb2, xc2;
                asm("mov.b64 %0, {%1, %1};" : "=l"(xa2) : "f"(fa));
                asm("mov.b64 %0, {%1, %1};" : "=l"(xb2) : "f"(fb));
                asm("mov.b64 %0, {%1, %1};" : "=l"(xc2) : "f"(fc));
                const ulonglong2* wr = (const ulonglong2*)(Wt + (kg * 4 + j) * C);
#pragma unroll
                for (int p = 0; p < C / 4; p++) {
                    const ulonglong2 w = wr[p];
                    asm("fma.rn.f32x2 %0, %1, %2, %0;" : "+l"(acc0[2*p  ]) : "l"(w.x), "l"(xa2));
                    asm("fma.rn.f32x2 %0, %1, %2, %0;" : "+l"(acc0[2*p+1]) : "l"(w.y), "l"(xa2));
                    asm("fma.rn.f32x2 %0, %1, %2, %0;" : "+l"(acc1[2*p  ]) : "l"(w.x), "l"(xb2));
                    asm("fma.rn.f32x2 %0, %1, %2, %0;" : "+l"(acc1[2*p+1]) : "l"(w.y), "l"(xb2));
                    asm("fma.rn.f32x2 %0, %1, %2, %0;" : "+l"(acc2[2*p  ]) : "l"(w.x), "l"(xc2));
                    asm("fma.rn.f32x2 %0, %1, %2, %0;" : "+l"(acc2[2*p+1]) : "l"(w.y), "l"(xc2));
                }
            }
            xa = na; xb = nb; xc = nc;
        }
    }

    float o0[C], o1[C], o2[C];
#pragma unroll
    for (int j = 0; j < C / 2; j++) {
        float lo, hi;
        asm("mov.b64 {%0, %1}, %2;" : "=f"(lo), "=f"(hi) : "l"(acc0[j]));
        o0[2*j] = lo + bs[2*j]; o0[2*j+1] = hi + bs[2*j+1];
        asm("mov.b64 {%0, %1}, %2;" : "=f"(lo), "=f"(hi) : "l"(acc1[j]));
        o1[2*j] = lo + bs[2*j]; o1[2*j+1] = hi + bs[2*j+1];
        asm("mov.b64 {%0, %1}, %2;" : "=f"(lo), "=f"(hi) : "l"(acc2[j]));
        o2[2*j] = lo + bs[2*j]; o2[2*j+1] = hi + bs[2*j+1];
    }
    float4* d0 = (float4*)(scores + (size_t)r0 * C);
#pragma unroll
    for (int c4 = 0; c4 < C / 4; c4++)
        d0[c4] = make_float4(o0[c4*4], o0[c4*4+1], o0[c4*4+2], o0[c4*4+3]);
    if (r1 < N_NODES) {
        float4* d1 = (float4*)(scores + (size_t)r1 * C);
#pragma unroll
        for (int c4 = 0; c4 < C / 4; c4++)
            d1[c4] = make_float4(o1[c4*4], o1[c4*4+1], o1[c4*4+2], o1[c4*4+3]);
    }
    if (r2 < N_NODES) {
        float4* d2 = (float4*)(scores + (size_t)r2 * C);
#pragma unroll
        for (int c4 = 0; c4 < C / 4; c4++)
            d2[c4] = make_float4(o2[c4*4], o2[c4*4+1], o2[c4*4+2], o2[c4*4+3]);
    }
}

// ============================================================
// 2) MLP -> h0 (fp16) + hs0 = inv_out*h0 (padded rows, bufA)
// ============================================================
#define MLP_BS 128
__global__ __launch_bounds__(MLP_BS) void mlp_kernel(
    const float* __restrict__ scores,
    const float* __restrict__ W1, const float* __restrict__ b1,
    const float* __restrict__ W2, const float* __restrict__ b2)
{
    __shared__ float W1s[C * H];
    __shared__ float W2s[H * C];
    __shared__ float b1s[H];
    __shared__ float b2s[C];
    __shared__ float p_sh[C * MLP_BS];

    const int tid = threadIdx.x;
    for (int i = tid; i < C * H; i += MLP_BS) W1s[i] = W1[i];
    for (int i = tid; i < H * C; i += MLP_BS) W2s[i] = W2[i];
    if (tid < H) b1s[tid] = b1[tid];
    if (tid < C) b2s[tid] = b2[tid];
    __syncthreads();

    const int node = blockIdx.x * MLP_BS + tid;
    if (node >= N_NODES) return;

    const float4* sc4 = (const float4*)(scores + (size_t)node * C);
    float m = -1e30f;
#pragma unroll
    for (int q = 0; q < C / 4; q++) {
        const float4 v = sc4[q];
        p_sh[(q * 4 + 0) * MLP_BS + tid] = v.x;
        p_sh[(q * 4 + 1) * MLP_BS + tid] = v.y;
        p_sh[(q * 4 + 2) * MLP_BS + tid] = v.z;
        p_sh[(q * 4 + 3) * MLP_BS + tid] = v.w;
        m = fmaxf(m, fmaxf(fmaxf(v.x, v.y), fmaxf(v.z, v.w)));
    }
    float s = 0.f;
    for (int i = 0; i < C; i++) {
        const float e = __expf(p_sh[i * MLP_BS + tid] - m);
        p_sh[i * MLP_BS + tid] = e;
        s += e;
    }
    const float inv = 1.f / s;

    float h1[H];
#pragma unroll
    for (int j = 0; j < H; j++) h1[j] = b1s[j];
    for (int i = 0; i < C; i++) {
        const float pv = p_sh[i * MLP_BS + tid] * inv;
#pragma unroll
        for (int j = 0; j < H; j++) h1[j] += pv * W1s[i * H + j];
    }
#pragma unroll
    for (int j = 0; j < H; j++) h1[j] = fmaxf(h1[j], 0.f);

    float o[C];
    for (int c = 0; c < C; c++) {
        float a = b2s[c];
#pragma unroll
        for (int j = 0; j < H; j++) a += h1[j] * W2s[j * C + c];
        o[c] = a;
    }

    const float2 iv = __ldg(&g_inv2[node]);
    uint4 pk_h[5], pk_s[5];
    uint32_t* ph = (uint32_t*)pk_h;
    uint32_t* ps = (uint32_t*)pk_s;
#pragma unroll
    for (int p = 0; p < C / 2; p++) {
        const __half2 hv = __floats2half2_rn(o[2*p], o[2*p+1]);
        ph[p] = *(const uint32_t*)&hv;
        const __half2 sv = __floats2half2_rn(o[2*p] * iv.y, o[2*p+1] * iv.y);
        ps[p] = *(const uint32_t*)&sv;
    }
    uint4* hr = (uint4*)(g_h0h + (size_t)node * C);
#pragma unroll
    for (int p = 0; p < 5; p++) hr[p] = pk_h[p];
    uint4* sr = g_bufA + (size_t)node * 8;
#pragma unroll
    for (int p = 0; p < 5; p++) sr[p] = pk_s[p];
}

// ============================================================
// 3) degrees (4 edges/thread, int4)
// ============================================================
__global__ void deg_kernel(const int4* __restrict__ src4, const int4* __restrict__ dst4)
{
    const int i = blockIdx.x * blockDim.x + threadIdx.x;
    if (i < N_EDGES / 4) {
        const int4 s = __ldg(src4 + i);
        const int4 d = __ldg(dst4 + i);
        atomicAdd(&g_deg[s.x], 1); atomicAdd(&g_deg[s.y], 1);
        atomicAdd(&g_deg[s.z], 1); atomicAdd(&g_deg[s.w], 1);
        atomicAdd(&g_deg[N_NODES + d.x], 1); atomicAdd(&g_deg[N_NODES + d.y], 1);
        atomicAdd(&g_deg[N_NODES + d.z], 1); atomicAdd(&g_deg[N_NODES + d.w], 1);
    }
}

// ============================================================
// 4) inv-sqrt -> packed float2 {inv_in, inv_out}  (REAL degrees)
// ============================================================
__global__ void invsqrt_kernel()
{
    const int i = blockIdx.x * blockDim.x + threadIdx.x;
    if (i < N_NODES) {
        const int d_o = g_deg[i];
        const int d_i = g_deg[N_NODES + i];
        g_inv2[i] = make_float2(d_i > 0 ? rsqrtf((float)d_i) : 0.f,
                                d_o > 0 ? rsqrtf((float)d_o) : 0.f);
    }
}

// padded degree: round deg_in up to multiple of 4
__device__ __forceinline__ int pdeg_of(int node)
{
    return (g_deg[N_NODES + node] + 3) & ~3;
}

// ============================================================
// 5) 3-phase parallel exclusive scan of PADDED deg -> g_off, g_cursor
// ============================================================
__global__ __launch_bounds__(256) void scan1_kernel()
{
    __shared__ int red[256];
    const int node = blockIdx.x * 256 + threadIdx.x;
    const int v = (node < N_NODES) ? pdeg_of(node) : 0;
    red[threadIdx.x] = v;
    __syncthreads();
#pragma unroll
    for (int o = 128; o > 0; o >>= 1) {
        if (threadIdx.x < o) red[threadIdx.x] += red[threadIdx.x + o];
        __syncthreads();
    }
    if (threadIdx.x == 0) g_part[blockIdx.x] = red[0];
}

__global__ __launch_bounds__(512) void scan2_kernel()
{
    __shared__ int sm[512];
    const int t = threadIdx.x;
    const int v = (t < NBLK) ? g_part[t] : 0;
    sm[t] = v;
    __syncthreads();
#pragma unroll
    for (int o = 1; o < 512; o <<= 1) {
        const int u = (t >= o) ? sm[t - o] : 0;
        __syncthreads();
        sm[t] += u;
        __syncthreads();
    }
    if (t < NBLK) g_base[t] = sm[t] - v;
    if (t == 511) g_off[N_NODES] = sm[511];
}

__global__ __launch_bounds__(256) void scan3_kernel()
{
    __shared__ int sm[256];
    const int node = blockIdx.x * 256 + threadIdx.x;
    const int v = (node < N_NODES) ? pdeg_of(node) : 0;
    sm[threadIdx.x] = v;
    __syncthreads();
#pragma unroll
    for (int o = 1; o < 256; o <<= 1) {
        const int u = (threadIdx.x >= o) ? sm[threadIdx.x - o] : 0;
        __syncthreads();
        sm[threadIdx.x] += u;
        __syncthreads();
    }
    if (node < N_NODES) {
        const int off = g_base[blockIdx.x] + sm[threadIdx.x] - v;
        g_off[node] = off;          // padded offset, %4 == 0
        g_cursor[node] = off;
    }
}

// ============================================================
// 6) counting sort of nodes by deg_in (64 bins) -> g_perm
// ============================================================
__global__ void hist_kernel()
{
    const int i = blockIdx.x * blockDim.x + threadIdx.x;
    if (i < N_NODES) {
        const int d = min(g_deg[N_NODES + i], BINS - 1);
        atomicAdd(&g_deg[2 * N_NODES + d], 1);
    }
}

__global__ __launch_bounds__(BINS) void binscan_kernel()
{
    __shared__ int sm[BINS];
    const int t = threadIdx.x;
    const int v = g_deg[2 * N_NODES + t];
    sm[t] = v;
    __syncthreads();
#pragma unroll
    for (int o = 1; o < BINS; o <<= 1) {
        const int u = (t >= o) ? sm[t - o] : 0;
        __syncthreads();
        sm[t] += u;
        __syncthreads();
    }
    g_deg[2 * N_NODES + BINS + t] = sm[t] - v;
}

__global__ void scatter_kernel()
{
    const int i = blockIdx.x * blockDim.x + threadIdx.x;
    if (i < N_NODES) {
        const int d = min(g_deg[N_NODES + i], BINS - 1);
        const int pos = atomicAdd(&g_deg[2 * N_NODES + BINS + d], 1);
        g_perm[pos] = i;
    }
}

// ============================================================
// 7) sentinel fill: every CSR slot defaults to the zero row,
//    then fill_csr overwrites the real edges.
// ============================================================
__global__ void sentinel_kernel()
{
    const int i = blockIdx.x * blockDim.x + threadIdx.x;
    if (i < CSR_CAP / 4)
        ((int4*)g_csr_src)[i] = make_int4(N_NODES, N_NODES, N_NODES, N_NODES);
}

__global__ void fill_csr_kernel(const int4* __restrict__ src4, const int4* __restrict__ dst4)
{
    const int i = blockIdx.x * blockDim.x + threadIdx.x;
    if (i < N_EDGES / 4) {
        const int4 s = __ldg(src4 + i);
        const int4 d = __ldg(dst4 + i);
        g_csr_src[atomicAdd(&g_cursor[d.x], 1)] = s.x;
        g_csr_src[atomicAdd(&g_cursor[d.y], 1)] = s.y;
        g_csr_src[atomicAdd(&g_cursor[d.z], 1)] = s.z;
        g_csr_src[atomicAdd(&g_cursor[d.w], 1)] = s.w;
    }
}

// ============================================================
// 8) one APPNP hop: 6 nodes/warp, 5 lanes/node, uint4/lane.
//    int4 src reads (padded CSR), sentinel gathers add 0.
// ============================================================
#define HOP_BS 256
#define NPW 6
#define NPB ((HOP_BS / 32) * NPW)            // 48 nodes per block

template <bool LAST>
__global__ __launch_bounds__(HOP_BS) void hop_kernel(
    const uint4* __restrict__ hs_in,
    uint4* __restrict__ hs_out, float* __restrict__ out_f)
{
    const int warp = threadIdx.x >> 5;
    const int lane = threadIdx.x & 31;
    const int sub = lane / 5;                // 0..5 active, lanes 30,31 idle
    const int q = lane - sub * 5;            // uint4 index within row
    if (sub >= NPW) return;

    const int idx = (blockIdx.x * (HOP_BS / 32) + warp) * NPW + sub;
    if (idx >= N_NODES) return;
    const int node = __ldg(&g_perm[idx]);

    const int beg4 = __ldg(&g_off[node]) >> 2;
    const int end4 = __ldg(&g_off[node + 1]) >> 2;

    float acc[8];
#pragma unroll
    for (int i = 0; i < 8; i++) acc[i] = 0.f;

    const int4* csr4 = (const int4*)g_csr_src;
#pragma unroll 2
    for (int e4 = beg4; e4 < end4; e4++) {
        const int4 s4 = __ldg(csr4 + e4);
#pragma unroll
        for (int g = 0; g < 4; g++) {
            const int s = g == 0 ? s4.x : g == 1 ? s4.y : g == 2 ? s4.z : s4.w;
            const uint4 hv = __ldg(hs_in + (size_t)s * 8 + q);
            const __half2* hp = (const __half2*)&hv;
#pragma unroll
            for (int i = 0; i < 4; i++) {
                const float2 f = __half22float2(hp[i]);
                acc[2 * i + 0] += f.x;
                acc[2 * i + 1] += f.y;
            }
        }
    }

    const float2 iv = __ldg(&g_inv2[node]);              // {inv_in, inv_out}
    const float w = (1.f - ALPHA) * iv.x;

    const uint4 h0v = __ldg((const uint4*)g_h0h + (size_t)node * 5 + q);
    const __half2* h0p = (const __half2*)&h0v;
    float o[8];
#pragma unroll
    for (int i = 0; i < 4; i++) {
        const float2 f = __half22float2(h0p[i]);
        o[2 * i + 0] = w * acc[2 * i + 0] + ALPHA * f.x;
        o[2 * i + 1] = w * acc[2 * i + 1] + ALPHA * f.y;
    }

    if (LAST) {
        float4* dst = (float4*)(out_f + (size_t)node * C + q * 8);
        dst[0] = make_float4(o[0], o[1], o[2], o[3]);
        dst[1] = make_float4(o[4], o[5], o[6], o[7]);
    } else {
        uint4 pk;
        uint32_t* pw = (uint32_t*)&pk;
#pragma unroll
        for (int i = 0; i < 4; i++) {
            const __half2 hv = __floats2half2_rn(o[2 * i] * iv.y, o[2 * i + 1] * iv.y);
            pw[i] = *(const uint32_t*)&hv;
        }
        hs_out[(size_t)node * 8 + q] = pk;
    }
}

// ============================================================
// launch
// ============================================================
extern "C" void kernel_launch(void* const* d_in, const int* in_sizes, int n_in,
                              void* d_out, int out_size)
{
    const float* x  = (const float*)d_in[0];
    const int*   ei = (const int*)d_in[1];
    const float* Wb = (const float*)d_in[2];
    const float* bb = (const float*)d_in[3];
    const float* W1 = (const float*)d_in[4];
    const float* b1 = (const float*)d_in[5];
    const float* W2 = (const float*)d_in[6];
    const float* b2 = (const float*)d_in[7];

    float* out = (float*)d_out;
    float* adjust = out;                              // [N, 40]
    float* scores = out + (size_t)N_NODES * C;        // [N, 40]

    const int4* src4 = (const int4*)ei;
    const int4* dst4 = (const int4*)(ei + N_EDGES);

    uint4 *Ap, *Bp;
    int *degp;
    cudaGetSymbolAddress((void**)&Ap, g_bufA);
    cudaGetSymbolAddress((void**)&Bp, g_bufB);
    cudaGetSymbolAddress((void**)&degp, g_deg);

    cudaMemsetAsync(degp, 0, (2 * N_NODES + 2 * BINS) * sizeof(int), 0);

    const int e4blk = (N_EDGES / 4 + 255) / 256;
    const int nblk  = (N_NODES + 255) / 256;

    // order: memset(1), deg(2), invsqrt(3), scan1(4), GEMM(5 - profiled), ...
    deg_kernel<<<e4blk, 256>>>(src4, dst4);
    invsqrt_kernel<<<nblk, 256>>>();
    scan1_kernel<<<NBLK, 256>>>();
    gemm_kernel<<<(N_NODES + ROWS3 - 1) / ROWS3, GB_T>>>(x, Wb, bb, scores);
    scan2_kernel<<<1, 512>>>();
    scan3_kernel<<<NBLK, 256>>>();
    hist_kernel<<<nblk, 256>>>();
    binscan_kernel<<<1, BINS>>>();
    scatter_kernel<<<nblk, 256>>>();
    sentinel_kernel<<<(CSR_CAP / 4 + 255) / 256, 256>>>();
    fill_csr_kernel<<<e4blk, 256>>>(src4, dst4);

    mlp_kernel<<<(N_NODES + MLP_BS - 1) / MLP_BS, MLP_BS>>>(scores, W1, b1, W2, b2);

    const int hop_grid = (N_NODES + NPB - 1) / NPB;
    const uint4* hin = Ap;                            // hs0 written by mlp
    for (int k = 0; k < K_HOPS; k++) {
        if (k == K_HOPS - 1) {
            hop_kernel<true><<<hop_grid, HOP_BS>>>(hin, nullptr, adjust);
        } else {
            uint4* o = (k % 2 == 0) ? Bp : Ap;        // first hop writes B
            hop_kernel<false><<<hop_grid, HOP_BS>>>(hin, o, nullptr);
            hin = o;
        }
    }
}

// round 12
// speedup vs baseline: 1.6861x; 1.0895x over previous
#include <cuda_runtime.h>
#include <cuda_fp16.h>
#include <cstdint>

// ---------------- problem constants ----------------
#define N_NODES 100000
#define N_EDGES 1600000
#define C_IN    500
#define C       40        // n_classes
#define H       64        // hidden
#define ALPHA   0.1f
#define K_HOPS  10
#define NBLK    391       // ceil(N_NODES/256)
#define BINS    64
#define CSR_CAP (N_EDGES + 3 * N_NODES)   // padded CSR capacity (1.9M, %4==0)

// ---------------- static scratch (no allocations allowed) ----------------
__device__ __half g_h0h[N_NODES * C];            // h0 (plain) fp16, 80B rows
// hs buffers: N_NODES+1 rows of 128B; row N_NODES is the SENTINEL ZERO ROW
__device__ __align__(128) uint4 g_bufA[(N_NODES + 1) * 8];
__device__ __align__(128) uint4 g_bufB[(N_NODES + 1) * 8];
// [0..N) deg_out, [N..2N) deg_in, [2N..2N+64) bin counts, [2N+64..2N+128) bin cursors
__device__ int     g_deg[2 * N_NODES + 2 * BINS];
__device__ float2  g_inv2[N_NODES];              // {inv_in, inv_out}
__device__ int     g_off[N_NODES + 1];           // PADDED offsets (%4==0)
__device__ int     g_cursor[N_NODES];
__device__ int     g_csr_src[CSR_CAP];           // src only; pad slots = N_NODES
__device__ int     g_perm[N_NODES];              // degree-sorted node order
__device__ int     g_part[512];
__device__ int     g_base[512];

// ============================================================
// 1) scores = x @ Wb + bb   [N, 40]  (R9-proven 2-row f32x2 version)
// ============================================================
#define GB_T 128
#define WKT  100
#define KG   (WKT / 4)

__global__ __launch_bounds__(GB_T, 3) void gemm_kernel(
    const float* __restrict__ x, const float* __restrict__ Wb,
    const float* __restrict__ bb, float* __restrict__ scores)
{
    __shared__ __align__(16) float Wt[WKT * C];
    __shared__ float bs[C];

    const int tid = threadIdx.x;
    if (tid < C) bs[tid] = bb[tid];

    const int r0 = blockIdx.x * 256 + tid;
    const int r1 = r0 + 128;
    const size_t r1c = (r1 < N_NODES) ? (size_t)r1 : (size_t)(N_NODES - 1);
    const float4* xa_p = (const float4*)(x + (size_t)r0 * C_IN);
    const float4* xb_p = (const float4*)(x + r1c * C_IN);

    unsigned long long acc0[C / 2], acc1[C / 2];
#pragma unroll
    for (int j = 0; j < C / 2; j++) { acc0[j] = 0ull; acc1[j] = 0ull; }

#pragma unroll 1
    for (int t = 0; t < C_IN / WKT; t++) {
        __syncthreads();
        const float4* wsrc = (const float4*)(Wb + t * WKT * C);
        for (int i = tid; i < WKT * C / 4; i += GB_T)
            ((float4*)Wt)[i] = wsrc[i];
        __syncthreads();

        float4 xa = __ldg(xa_p + t * KG);
        float4 xb = __ldg(xb_p + t * KG);
#pragma unroll 1
        for (int kg = 0; kg < KG; kg++) {
            const int nidx = (kg + 1 < KG) ? kg + 1 : kg;
            const float4 na = __ldg(xa_p + t * KG + nidx);
            const float4 nb = __ldg(xb_p + t * KG + nidx);
#pragma unroll
            for (int j = 0; j < 4; j++) {
                const float fa = j == 0 ? xa.x : j == 1 ? xa.y : j == 2 ? xa.z : xa.w;
                const float fb = j == 0 ? xb.x : j == 1 ? xb.y : j == 2 ? xb.z : xb.w;
                unsigned long long xa2, xb2;
                asm("mov.b64 %0, {%1, %1};" : "=l"(xa2) : "f"(fa));
                asm("mov.b64 %0, {%1, %1};" : "=l"(xb2) : "f"(fb));
                const ulonglong2* wr = (const ulonglong2*)(Wt + (kg * 4 + j) * C);
#pragma unroll
                for (int p = 0; p < C / 4; p++) {
                    const ulonglong2 w = wr[p];
                    asm("fma.rn.f32x2 %0, %1, %2, %0;" : "+l"(acc0[2*p  ]) : "l"(w.x), "l"(xa2));
                    asm("fma.rn.f32x2 %0, %1, %2, %0;" : "+l"(acc0[2*p+1]) : "l"(w.y), "l"(xa2));
                    asm("fma.rn.f32x2 %0, %1, %2, %0;" : "+l"(acc1[2*p  ]) : "l"(w.x), "l"(xb2));
                    asm("fma.rn.f32x2 %0, %1, %2, %0;" : "+l"(acc1[2*p+1]) : "l"(w.y), "l"(xb2));
                }
            }
            xa = na; xb = nb;
        }
    }

    float o0[C], o1[C];
#pragma unroll
    for (int j = 0; j < C / 2; j++) {
        float lo, hi;
        asm("mov.b64 {%0, %1}, %2;" : "=f"(lo), "=f"(hi) : "l"(acc0[j]));
        o0[2*j] = lo + bs[2*j]; o0[2*j+1] = hi + bs[2*j+1];
        asm("mov.b64 {%0, %1}, %2;" : "=f"(lo), "=f"(hi) : "l"(acc1[j]));
        o1[2*j] = lo + bs[2*j]; o1[2*j+1] = hi + bs[2*j+1];
    }
    float4* d0 = (float4*)(scores + (size_t)r0 * C);
#pragma unroll
    for (int c4 = 0; c4 < C / 4; c4++)
        d0[c4] = make_float4(o0[c4*4], o0[c4*4+1], o0[c4*4+2], o0[c4*4+3]);
    if (r1 < N_NODES) {
        float4* d1 = (float4*)(scores + (size_t)r1 * C);
#pragma unroll
        for (int c4 = 0; c4 < C / 4; c4++)
            d1[c4] = make_float4(o1[c4*4], o1[c4*4+1], o1[c4*4+2], o1[c4*4+3]);
    }
}

// ============================================================
// 2) MLP -> h0 (fp16) + hs0 = inv_out*h0 (padded rows, bufA)
// ============================================================
#define MLP_BS 128
__global__ __launch_bounds__(MLP_BS) void mlp_kernel(
    const float* __restrict__ scores,
    const float* __restrict__ W1, const float* __restrict__ b1,
    const float* __restrict__ W2, const float* __restrict__ b2)
{
    __shared__ float W1s[C * H];
    __shared__ float W2s[H * C];
    __shared__ float b1s[H];
    __shared__ float b2s[C];
    __shared__ float p_sh[C * MLP_BS];

    const int tid = threadIdx.x;
    for (int i = tid; i < C * H; i += MLP_BS) W1s[i] = W1[i];
    for (int i = tid; i < H * C; i += MLP_BS) W2s[i] = W2[i];
    if (tid < H) b1s[tid] = b1[tid];
    if (tid < C) b2s[tid] = b2[tid];
    __syncthreads();

    const int node = blockIdx.x * MLP_BS + tid;
    if (node >= N_NODES) return;

    const float4* sc4 = (const float4*)(scores + (size_t)node * C);
    float m = -1e30f;
#pragma unroll
    for (int q = 0; q < C / 4; q++) {
        const float4 v = sc4[q];
        p_sh[(q * 4 + 0) * MLP_BS + tid] = v.x;
        p_sh[(q * 4 + 1) * MLP_BS + tid] = v.y;
        p_sh[(q * 4 + 2) * MLP_BS + tid] = v.z;
        p_sh[(q * 4 + 3) * MLP_BS + tid] = v.w;
        m = fmaxf(m, fmaxf(fmaxf(v.x, v.y), fmaxf(v.z, v.w)));
    }
    float s = 0.f;
    for (int i = 0; i < C; i++) {
        const float e = __expf(p_sh[i * MLP_BS + tid] - m);
        p_sh[i * MLP_BS + tid] = e;
        s += e;
    }
    const float inv = 1.f / s;

    float h1[H];
#pragma unroll
    for (int j = 0; j < H; j++) h1[j] = b1s[j];
    for (int i = 0; i < C; i++) {
        const float pv = p_sh[i * MLP_BS + tid] * inv;
#pragma unroll
        for (int j = 0; j < H; j++) h1[j] += pv * W1s[i * H + j];
    }
#pragma unroll
    for (int j = 0; j < H; j++) h1[j] = fmaxf(h1[j], 0.f);

    float o[C];
    for (int c = 0; c < C; c++) {
        float a = b2s[c];
#pragma unroll
        for (int j = 0; j < H; j++) a += h1[j] * W2s[j * C + c];
        o[c] = a;
    }

    const float2 iv = __ldg(&g_inv2[node]);
    uint4 pk_h[5], pk_s[5];
    uint32_t* ph = (uint32_t*)pk_h;
    uint32_t* ps = (uint32_t*)pk_s;
#pragma unroll
    for (int p = 0; p < C / 2; p++) {
        const __half2 hv = __floats2half2_rn(o[2*p], o[2*p+1]);
        ph[p] = *(const uint32_t*)&hv;
        const __half2 sv = __floats2half2_rn(o[2*p] * iv.y, o[2*p+1] * iv.y);
        ps[p] = *(const uint32_t*)&sv;
    }
    uint4* hr = (uint4*)(g_h0h + (size_t)node * C);
#pragma unroll
    for (int p = 0; p < 5; p++) hr[p] = pk_h[p];
    uint4* sr = g_bufA + (size_t)node * 8;
#pragma unroll
    for (int p = 0; p < 5; p++) sr[p] = pk_s[p];
}

// ============================================================
// 3) degrees (4 edges/thread, int4)
// ============================================================
__global__ void deg_kernel(const int4* __restrict__ src4, const int4* __restrict__ dst4)
{
    const int i = blockIdx.x * blockDim.x + threadIdx.x;
    if (i < N_EDGES / 4) {
        const int4 s = __ldg(src4 + i);
        const int4 d = __ldg(dst4 + i);
        atomicAdd(&g_deg[s.x], 1); atomicAdd(&g_deg[s.y], 1);
        atomicAdd(&g_deg[s.z], 1); atomicAdd(&g_deg[s.w], 1);
        atomicAdd(&g_deg[N_NODES + d.x], 1); atomicAdd(&g_deg[N_NODES + d.y], 1);
        atomicAdd(&g_deg[N_NODES + d.z], 1); atomicAdd(&g_deg[N_NODES + d.w], 1);
    }
}

// ============================================================
// 4) inv-sqrt -> packed float2 {inv_in, inv_out}  (REAL degrees)
// ============================================================
__global__ void invsqrt_kernel()
{
    const int i = blockIdx.x * blockDim.x + threadIdx.x;
    if (i < N_NODES) {
        const int d_o = g_deg[i];
        const int d_i = g_deg[N_NODES + i];
        g_inv2[i] = make_float2(d_i > 0 ? rsqrtf((float)d_i) : 0.f,
                                d_o > 0 ? rsqrtf((float)d_o) : 0.f);
    }
}

// padded degree: round deg_in up to multiple of 4
__device__ __forceinline__ int pdeg_of(int node)
{
    return (g_deg[N_NODES + node] + 3) & ~3;
}

// ============================================================
// 5) 3-phase parallel exclusive scan of PADDED deg -> g_off, g_cursor
// ============================================================
__global__ __launch_bounds__(256) void scan1_kernel()
{
    __shared__ int red[256];
    const int node = blockIdx.x * 256 + threadIdx.x;
    const int v = (node < N_NODES) ? pdeg_of(node) : 0;
    red[threadIdx.x] = v;
    __syncthreads();
#pragma unroll
    for (int o = 128; o > 0; o >>= 1) {
        if (threadIdx.x < o) red[threadIdx.x] += red[threadIdx.x + o];
        __syncthreads();
    }
    if (threadIdx.x == 0) g_part[blockIdx.x] = red[0];
}

__global__ __launch_bounds__(512) void scan2_kernel()
{
    __shared__ int sm[512];
    const int t = threadIdx.x;
    const int v = (t < NBLK) ? g_part[t] : 0;
    sm[t] = v;
    __syncthreads();
#pragma unroll
    for (int o = 1; o < 512; o <<= 1) {
        const int u = (t >= o) ? sm[t - o] : 0;
        __syncthreads();
        sm[t] += u;
        __syncthreads();
    }
    if (t < NBLK) g_base[t] = sm[t] - v;
    if (t == 511) g_off[N_NODES] = sm[511];
}

__global__ __launch_bounds__(256) void scan3_kernel()
{
    __shared__ int sm[256];
    const int node = blockIdx.x * 256 + threadIdx.x;
    const int v = (node < N_NODES) ? pdeg_of(node) : 0;
    sm[threadIdx.x] = v;
    __syncthreads();
#pragma unroll
    for (int o = 1; o < 256; o <<= 1) {
        const int u = (threadIdx.x >= o) ? sm[threadIdx.x - o] : 0;
        __syncthreads();
        sm[threadIdx.x] += u;
        __syncthreads();
    }
    if (node < N_NODES) {
        const int off = g_base[blockIdx.x] + sm[threadIdx.x] - v;
        g_off[node] = off;
        g_cursor[node] = off;
    }
}

// ============================================================
// 6) counting sort of nodes by deg_in (64 bins) -> g_perm
// ============================================================
__global__ void hist_kernel()
{
    const int i = blockIdx.x * blockDim.x + threadIdx.x;
    if (i < N_NODES) {
        const int d = min(g_deg[N_NODES + i], BINS - 1);
        atomicAdd(&g_deg[2 * N_NODES + d], 1);
    }
}

__global__ __launch_bounds__(BINS) void binscan_kernel()
{
    __shared__ int sm[BINS];
    const int t = threadIdx.x;
    const int v = g_deg[2 * N_NODES + t];
    sm[t] = v;
    __syncthreads();
#pragma unroll
    for (int o = 1; o < BINS; o <<= 1) {
        const int u = (t >= o) ? sm[t - o] : 0;
        __syncthreads();
        sm[t] += u;
        __syncthreads();
    }
    g_deg[2 * N_NODES + BINS + t] = sm[t] - v;
}

__global__ void scatter_kernel()
{
    const int i = blockIdx.x * blockDim.x + threadIdx.x;
    if (i < N_NODES) {
        const int d = min(g_deg[N_NODES + i], BINS - 1);
        const int pos = atomicAdd(&g_deg[2 * N_NODES + BINS + d], 1);
        g_perm[pos] = i;
    }
}

// ============================================================
// 7) sentinel fill + CSR fill
// ============================================================
__global__ void sentinel_kernel()
{
    const int i = blockIdx.x * blockDim.x + threadIdx.x;
    if (i < CSR_CAP / 4)
        ((int4*)g_csr_src)[i] = make_int4(N_NODES, N_NODES, N_NODES, N_NODES);
}

__global__ void fill_csr_kernel(const int4* __restrict__ src4, const int4* __restrict__ dst4)
{
    const int i = blockIdx.x * blockDim.x + threadIdx.x;
    if (i < N_EDGES / 4) {
        const int4 s = __ldg(src4 + i);
        const int4 d = __ldg(dst4 + i);
        g_csr_src[atomicAdd(&g_cursor[d.x], 1)] = s.x;
        g_csr_src[atomicAdd(&g_cursor[d.y], 1)] = s.y;
        g_csr_src[atomicAdd(&g_cursor[d.z], 1)] = s.z;
        g_csr_src[atomicAdd(&g_cursor[d.w], 1)] = s.w;
    }
}

// ============================================================
// 8) one APPNP hop: 6 nodes/warp, 5 lanes/node, uint4/lane.
//    int4 src reads (padded CSR), sentinel gathers add 0.
// ============================================================
#define HOP_BS 256
#define NPW 6
#define NPB ((HOP_BS / 32) * NPW)            // 48 nodes per block

template <bool LAST>
__global__ __launch_bounds__(HOP_BS) void hop_kernel(
    const uint4* __restrict__ hs_in,
    uint4* __restrict__ hs_out, float* __restrict__ out_f)
{
    const int warp = threadIdx.x >> 5;
    const int lane = threadIdx.x & 31;
    const int sub = lane / 5;
    const int q = lane - sub * 5;
    if (sub >= NPW) return;

    const int idx = (blockIdx.x * (HOP_BS / 32) + warp) * NPW + sub;
    if (idx >= N_NODES) return;
    const int node = __ldg(&g_perm[idx]);

    const int beg4 = __ldg(&g_off[node]) >> 2;
    const int end4 = __ldg(&g_off[node + 1]) >> 2;

    float acc[8];
#pragma unroll
    for (int i = 0; i < 8; i++) acc[i] = 0.f;

    const int4* csr4 = (const int4*)g_csr_src;
#pragma unroll 2
    for (int e4 = beg4; e4 < end4; e4++) {
        const int4 s4 = __ldg(csr4 + e4);
#pragma unroll
        for (int g = 0; g < 4; g++) {
            const int s = g == 0 ? s4.x : g == 1 ? s4.y : g == 2 ? s4.z : s4.w;
            const uint4 hv = __ldg(hs_in + (size_t)s * 8 + q);
            const __half2* hp = (const __half2*)&hv;
#pragma unroll
            for (int i = 0; i < 4; i++) {
                const float2 f = __half22float2(hp[i]);
                acc[2 * i + 0] += f.x;
                acc[2 * i + 1] += f.y;
            }
        }
    }

    const float2 iv = __ldg(&g_inv2[node]);
    const float w = (1.f - ALPHA) * iv.x;

    const uint4 h0v = __ldg((const uint4*)g_h0h + (size_t)node * 5 + q);
    const __half2* h0p = (const __half2*)&h0v;
    float o[8];
#pragma unroll
    for (int i = 0; i < 4; i++) {
        const float2 f = __half22float2(h0p[i]);
        o[2 * i + 0] = w * acc[2 * i + 0] + ALPHA * f.x;
        o[2 * i + 1] = w * acc[2 * i + 1] + ALPHA * f.y;
    }

    if (LAST) {
        float4* dst = (float4*)(out_f + (size_t)node * C + q * 8);
        dst[0] = make_float4(o[0], o[1], o[2], o[3]);
        dst[1] = make_float4(o[4], o[5], o[6], o[7]);
    } else {
        uint4 pk;
        uint32_t* pw = (uint32_t*)&pk;
#pragma unroll
        for (int i = 0; i < 4; i++) {
            const __half2 hv = __floats2half2_rn(o[2 * i] * iv.y, o[2 * i + 1] * iv.y);
            pw[i] = *(const uint32_t*)&hv;
        }
        hs_out[(size_t)node * 8 + q] = pk;
    }
}

// ============================================================
// launch — prep forked to a second stream, overlapped with
// gemm+mlp. Stream/events created fresh each call (kernel_launch
// only runs for the correctness pass + the capture pass).
// ============================================================
extern "C" void kernel_launch(void* const* d_in, const int* in_sizes, int n_in,
                              void* d_out, int out_size)
{
    const float* x  = (const float*)d_in[0];
    const int*   ei = (const int*)d_in[1];
    const float* Wb = (const float*)d_in[2];
    const float* bb = (const float*)d_in[3];
    const float* W1 = (const float*)d_in[4];
    const float* b1 = (const float*)d_in[5];
    const float* W2 = (const float*)d_in[6];
    const float* b2 = (const float*)d_in[7];

    float* out = (float*)d_out;
    float* adjust = out;                              // [N, 40]
    float* scores = out + (size_t)N_NODES * C;        // [N, 40]

    const int4* src4 = (const int4*)ei;
    const int4* dst4 = (const int4*)(ei + N_EDGES);

    uint4 *Ap, *Bp;
    int *degp;
    cudaGetSymbolAddress((void**)&Ap, g_bufA);
    cudaGetSymbolAddress((void**)&Bp, g_bufB);
    cudaGetSymbolAddress((void**)&degp, g_deg);

    cudaStream_t s2;
    cudaStreamCreateWithFlags(&s2, cudaStreamNonBlocking);
    cudaEvent_t e_fork, e_inv, e_csr;
    cudaEventCreateWithFlags(&e_fork, cudaEventDisableTiming);
    cudaEventCreateWithFlags(&e_inv, cudaEventDisableTiming);
    cudaEventCreateWithFlags(&e_csr, cudaEventDisableTiming);

    const int e4blk = (N_EDGES / 4 + 255) / 256;
    const int nblk  = (N_NODES + 255) / 256;

    // main stream: memset, then fork
    cudaMemsetAsync(degp, 0, (2 * N_NODES + 2 * BINS) * sizeof(int), 0);
    cudaEventRecord(e_fork, 0);
    cudaStreamWaitEvent(s2, e_fork, 0);

    // prep chain on s2
    deg_kernel<<<e4blk, 256, 0, s2>>>(src4, dst4);
    invsqrt_kernel<<<nblk, 256, 0, s2>>>();
    cudaEventRecord(e_inv, s2);                       // inv2 ready (mlp needs it)
    scan1_kernel<<<NBLK, 256, 0, s2>>>();
    scan2_kernel<<<1, 512, 0, s2>>>();
    scan3_kernel<<<NBLK, 256, 0, s2>>>();
    hist_kernel<<<nblk, 256, 0, s2>>>();
    binscan_kernel<<<1, BINS, 0, s2>>>();
    scatter_kernel<<<nblk, 256, 0, s2>>>();
    sentinel_kernel<<<(CSR_CAP / 4 + 255) / 256, 256, 0, s2>>>();
    fill_csr_kernel<<<e4blk, 256, 0, s2>>>(src4, dst4);
    cudaEventRecord(e_csr, s2);                       // CSR + perm ready

    // main stream: gemm runs concurrently with prep
    gemm_kernel<<<(N_NODES + 255) / 256, GB_T>>>(x, Wb, bb, scores);
    cudaStreamWaitEvent(0, e_inv, 0);                 // mlp needs inv2
    mlp_kernel<<<(N_NODES + MLP_BS - 1) / MLP_BS, MLP_BS>>>(scores, W1, b1, W2, b2);
    cudaStreamWaitEvent(0, e_csr, 0);                 // hops need CSR (join)

    const int hop_grid = (N_NODES + NPB - 1) / NPB;
    const uint4* hin = Ap;                            // hs0 written by mlp
    for (int k = 0; k < K_HOPS; k++) {
        if (k == K_HOPS - 1) {
            hop_kernel<true><<<hop_grid, HOP_BS>>>(hin, nullptr, adjust);
        } else {
            uint4* o = (k % 2 == 0) ? Bp : Ap;
            hop_kernel<false><<<hop_grid, HOP_BS>>>(hin, o, nullptr);
            hin = o;
        }
    }
}